// round 1
// baseline (speedup 1.0000x reference)
#include <cuda_runtime.h>
#include <cstdint>

#define MTOT 8192      // B*S = 4*2048
#define DIN  4096
#define DOUT 4096
#define NADPT 8
#define RANK 16
#define NR   128       // NADPT*RANK
#define LORA_SCALE 2.0f  // ALPHA/RANK = 32/16

// scratch (allocation-free rule: __device__ globals)
__device__ float g_h[MTOT * NR];    // 4 MB: low-rank activations
__device__ float g_Bc[DOUT * NR];   // 2 MB: coef-fused concatenated B

__device__ __forceinline__ float f2tf(float x) {
    unsigned r;
    asm("cvt.rna.tf32.f32 %0, %1;" : "=r"(r) : "f"(x));
    return __uint_as_float(r);
}

// Bc[o][n*16+r] = SCALE * lw[n] * lora_B[n][o][r]
__global__ void build_bc_kernel(const float* __restrict__ lora_B,
                                const float* __restrict__ lw) {
    int idx = blockIdx.x * blockDim.x + threadIdx.x;
    if (idx >= DOUT * NR) return;
    int o  = idx / NR;
    int nr = idx - o * NR;
    int n  = nr >> 4;
    int r  = nr & 15;
    g_Bc[idx] = (LORA_SCALE * lw[n]) * lora_B[((size_t)n * DOUT + o) * RANK + r];
}

// C[M, gridDim.x*128] = A[M,K1] @ B1[:,K1]^T  (+ A2[M,K2] @ B2[:,K2]^T) (+ bias)
// A2/B2 have leading dim NR. BN=128, BK=32, 256 threads, warps 2x4.
template<int BM>
__global__ __launch_bounds__(256)
void gemm_tf32_kernel(const float* __restrict__ A, int lda,
                      const float* __restrict__ B1, int ldb,
                      int K1,
                      const float* __restrict__ A2,
                      const float* __restrict__ B2,
                      int K2,
                      const float* __restrict__ bias,
                      float* __restrict__ C, int ldc)
{
    constexpr int MI   = BM / 32;   // 16-row mma tiles per warp in M
    constexpr int LDS_ = 36;        // padded leading dim (conflict-free, float4-aligned)
    __shared__ float As[BM  * LDS_];
    __shared__ float Bs[128 * LDS_];

    const int tid    = threadIdx.x;
    const int wid    = tid >> 5;
    const int lane   = tid & 31;
    const int gid    = lane >> 2;   // group id 0..7
    const int tig    = lane & 3;    // thread in group
    const int warp_m = wid >> 2;    // 0..1
    const int warp_n = wid & 3;     // 0..3

    const int mBase = blockIdx.y * BM;
    const int nBase = blockIdx.x * 128;

    float acc[MI][4][4];
    #pragma unroll
    for (int i = 0; i < MI; i++)
        #pragma unroll
        for (int j = 0; j < 4; j++)
            #pragma unroll
            for (int k = 0; k < 4; k++) acc[i][j][k] = 0.f;

    const int warpRow = warp_m * (BM / 2);
    const int warpCol = warp_n * 32;

    #pragma unroll 1
    for (int seg = 0; seg < 2; seg++) {
        const float* Ap; const float* Bp; int K, ldA, ldB;
        if (seg == 0) { Ap = A;  Bp = B1; K = K1; ldA = lda; ldB = ldb; }
        else          { Ap = A2; Bp = B2; K = K2; ldA = NR;  ldB = NR;  }
        if (K == 0 || Ap == nullptr) continue;

        for (int kb = 0; kb < K; kb += 32) {
            __syncthreads();
            // ---- load A tile: BM x 32 (rounded to tf32 at store) ----
            #pragma unroll
            for (int it = 0; it < (BM * 8) / 256; it++) {
                int i   = it * 256 + tid;
                int row = i >> 3, c4 = (i & 7) << 2;
                float4 v = *reinterpret_cast<const float4*>(
                    Ap + (size_t)(mBase + row) * ldA + kb + c4);
                float* d = &As[row * LDS_ + c4];
                d[0] = f2tf(v.x); d[1] = f2tf(v.y);
                d[2] = f2tf(v.z); d[3] = f2tf(v.w);
            }
            // ---- load B tile: 128 x 32 ----
            #pragma unroll
            for (int it = 0; it < 4; it++) {
                int i   = it * 256 + tid;
                int row = i >> 3, c4 = (i & 7) << 2;
                float4 v = *reinterpret_cast<const float4*>(
                    Bp + (size_t)(nBase + row) * ldB + kb + c4);
                float* d = &Bs[row * LDS_ + c4];
                d[0] = f2tf(v.x); d[1] = f2tf(v.y);
                d[2] = f2tf(v.z); d[3] = f2tf(v.w);
            }
            __syncthreads();

            #pragma unroll
            for (int ks = 0; ks < 4; ks++) {
                unsigned af[MI][4], bf[4][2];
                #pragma unroll
                for (int mi = 0; mi < MI; mi++) {
                    int r0 = (warpRow + mi * 16 + gid) * LDS_ + ks * 8 + tig;
                    af[mi][0] = __float_as_uint(As[r0]);
                    af[mi][1] = __float_as_uint(As[r0 + 8 * LDS_]);
                    af[mi][2] = __float_as_uint(As[r0 + 4]);
                    af[mi][3] = __float_as_uint(As[r0 + 8 * LDS_ + 4]);
                }
                #pragma unroll
                for (int ni = 0; ni < 4; ni++) {
                    int r0 = (warpCol + ni * 8 + gid) * LDS_ + ks * 8 + tig;
                    bf[ni][0] = __float_as_uint(Bs[r0]);
                    bf[ni][1] = __float_as_uint(Bs[r0 + 4]);
                }
                #pragma unroll
                for (int mi = 0; mi < MI; mi++)
                    #pragma unroll
                    for (int ni = 0; ni < 4; ni++) {
                        asm volatile(
                            "mma.sync.aligned.m16n8k8.row.col.f32.tf32.tf32.f32 "
                            "{%0,%1,%2,%3}, {%4,%5,%6,%7}, {%8,%9}, {%0,%1,%2,%3};"
                            : "+f"(acc[mi][ni][0]), "+f"(acc[mi][ni][1]),
                              "+f"(acc[mi][ni][2]), "+f"(acc[mi][ni][3])
                            : "r"(af[mi][0]), "r"(af[mi][1]),
                              "r"(af[mi][2]), "r"(af[mi][3]),
                              "r"(bf[ni][0]), "r"(bf[ni][1]));
                    }
            }
        }
    }

    // ---- epilogue: +bias, store fp32 ----
    #pragma unroll
    for (int mi = 0; mi < MI; mi++) {
        int row = mBase + warpRow + mi * 16 + gid;
        #pragma unroll
        for (int ni = 0; ni < 4; ni++) {
            int col = nBase + warpCol + ni * 8 + tig * 2;
            float b0 = bias ? bias[col]     : 0.f;
            float b1 = bias ? bias[col + 1] : 0.f;
            C[(size_t)row * ldc + col]           = acc[mi][ni][0] + b0;
            C[(size_t)row * ldc + col + 1]       = acc[mi][ni][1] + b1;
            C[(size_t)(row + 8) * ldc + col]     = acc[mi][ni][2] + b0;
            C[(size_t)(row + 8) * ldc + col + 1] = acc[mi][ni][3] + b1;
        }
    }
}

extern "C" void kernel_launch(void* const* d_in, const int* in_sizes, int n_in,
                              void* d_out, int out_size) {
    const float* x      = (const float*)d_in[0];  // [4,2048,4096]
    const float* lora_A = (const float*)d_in[1];  // [8,16,4096] -> flat [128,4096]
    const float* lora_B = (const float*)d_in[2];  // [8,4096,16]
    const float* W      = (const float*)d_in[3];  // [4096,4096]
    const float* bias   = (const float*)d_in[4];  // [4096]
    const float* lw     = (const float*)d_in[5];  // [8]
    float* out = (float*)d_out;                   // [8192,4096]

    float* hbuf = nullptr;
    float* bcb  = nullptr;
    cudaGetSymbolAddress((void**)&hbuf, g_h);
    cudaGetSymbolAddress((void**)&bcb,  g_Bc);

    // 1) Bc = coef-fused lora_B gather: [4096,128]
    build_bc_kernel<<<(DOUT * NR + 255) / 256, 256>>>(lora_B, lw);

    // 2) h = x @ A_flat^T : [8192,128], K=4096
    gemm_tf32_kernel<64><<<dim3(1, MTOT / 64), 256>>>(
        x, DIN, lora_A, DIN, DIN,
        nullptr, nullptr, 0,
        nullptr, hbuf, NR);

    // 3) out = x @ W^T + h @ Bc^T + bias : [8192,4096]
    gemm_tf32_kernel<128><<<dim3(DOUT / 128, MTOT / 128), 256>>>(
        x, DIN, W, DIN, DIN,
        hbuf, bcb, NR,
        bias, out, DOUT);
}

// round 3
// speedup vs baseline: 1.0151x; 1.0151x over previous
#include <cuda_runtime.h>
#include <cstdint>

#define MTOT 8192      // B*S
#define DIN  4096
#define DOUT 4096
#define RANK 16
#define NR   128       // N_adapters * RANK
#define LORA_SCALE 2.0f

// ---- scratch (__device__ globals per allocation rules) ----
__device__ float g_x[MTOT * DIN];   // tf32-rounded x
__device__ float g_W[DOUT * DIN];   // tf32-rounded W
__device__ float g_A[NR * DIN];     // tf32-rounded lora_A
__device__ float g_h[MTOT * NR];    // low-rank acts (tf32-rounded)
__device__ float g_Bc[DOUT * NR];   // coef-fused lora_B (tf32-rounded)

__device__ __forceinline__ float f2tf(float x) {
    unsigned r; asm("cvt.rna.tf32.f32 %0, %1;" : "=r"(r) : "f"(x));
    return __uint_as_float(r);
}
__device__ __forceinline__ uint32_t s2u(const void* p) {
    return (uint32_t)__cvta_generic_to_shared(p);
}
__device__ __forceinline__ void cp16(uint32_t dst, const float* src) {
    asm volatile("cp.async.cg.shared.global [%0], [%1], 16;\n"
                 :: "r"(dst), "l"(src));
}
__device__ __forceinline__ void cp_commit() {
    asm volatile("cp.async.commit_group;" ::: "memory");
}
template<int N>
__device__ __forceinline__ void cp_wait() {
    asm volatile("cp.async.wait_group %0;" :: "n"(N) : "memory");
}

// ---- elementwise tf32-RNA rounding, float4 grid-stride ----
__global__ void round_tf32_kernel(const float4* __restrict__ in,
                                  float4* __restrict__ out, int n4) {
    for (int i = blockIdx.x * blockDim.x + threadIdx.x; i < n4;
         i += gridDim.x * blockDim.x) {
        float4 v = in[i];
        v.x = f2tf(v.x); v.y = f2tf(v.y); v.z = f2tf(v.z); v.w = f2tf(v.w);
        out[i] = v;
    }
}

// Bc[o][n*16+r] = tf32(SCALE * lw[n] * lora_B[n][o][r])
__global__ void build_bc_kernel(const float* __restrict__ lora_B,
                                const float* __restrict__ lw) {
    int idx = blockIdx.x * blockDim.x + threadIdx.x;
    if (idx >= DOUT * NR) return;
    int o  = idx / NR;
    int nr = idx - o * NR;
    int n  = nr >> 4;
    int r  = nr & 15;
    g_Bc[idx] = f2tf((LORA_SCALE * lw[n]) * lora_B[((size_t)n * DOUT + o) * RANK + r]);
}

// ============================================================================
// mma.sync tf32 GEMM, 3-stage cp.async pipeline.
// BMxBN = BMx128, BK=32, 256 threads (warps 2x4, warp tile (BM/2)x32).
// C[M,N] = A1[M,K1]@B1[N,K1]^T (+ A2[M,K2]@B2[N,K2]^T, ld=NR) (+ bias)
// Inputs must already be tf32-rounded (HW truncation is then exact).
// ============================================================================
template<int BM>
__global__ __launch_bounds__(256, 1)
void gemm_tf32_pipe(const float* __restrict__ A1, int lda1,
                    const float* __restrict__ B1, int ldb1, int K1,
                    const float* __restrict__ A2, const float* __restrict__ B2,
                    int K2,
                    const float* __restrict__ bias,
                    float* __restrict__ C, int ldc, int round_out)
{
    constexpr int BN   = 128;
    constexpr int S    = 3;                       // pipeline stages
    constexpr int MI   = BM / 32;                 // 16-row mma tiles per warp
    constexpr int LDS_ = 36;                      // padded lead (floats)
    constexpr int AST  = BM * LDS_;               // A stage size (floats)
    constexpr int BST  = BN * LDS_;
    constexpr int STG  = AST + BST;

    extern __shared__ float smem[];               // S * STG floats

    const int tid    = threadIdx.x;
    const int wid    = tid >> 5;
    const int lane   = tid & 31;
    const int gid    = lane >> 2;
    const int tig    = lane & 3;
    const int warp_m = wid >> 2;                  // 0..1
    const int warp_n = wid & 3;                   // 0..3
    const int warpRow = warp_m * (BM / 2);
    const int warpCol = warp_n * 32;

    const size_t mBase = (size_t)blockIdx.y * BM;
    const size_t nBase = (size_t)blockIdx.x * BN;

    const int n1    = K1 / 32;
    const int nIter = n1 + K2 / 32;

    // per-thread cp.async source row/col (fixed across stages)
    // A: BM*8 chunks; B: 128*8 chunks; each thread does BM*8/256 + 4 chunks
    const uint32_t smemB = s2u(smem);

    auto issue = [&](int k) {
        int slot = k % S;
        uint32_t aS = smemB + slot * STG * 4;
        uint32_t bS = aS + AST * 4;
        const float *Ap, *Bp; int ldA, ldB, kk;
        if (k < n1) { Ap = A1; Bp = B1; ldA = lda1; ldB = ldb1; kk = k * 32; }
        else        { Ap = A2; Bp = B2; ldA = NR;   ldB = NR;   kk = (k - n1) * 32; }
        #pragma unroll
        for (int i = 0; i < (BM * 8) / 256; i++) {
            int idx = tid + i * 256, row = idx >> 3, c4 = (idx & 7) << 2;
            cp16(aS + (row * LDS_ + c4) * 4,
                 Ap + (mBase + row) * (size_t)ldA + kk + c4);
        }
        #pragma unroll
        for (int i = 0; i < 4; i++) {
            int idx = tid + i * 256, row = idx >> 3, c4 = (idx & 7) << 2;
            cp16(bS + (row * LDS_ + c4) * 4,
                 Bp + (nBase + row) * (size_t)ldB + kk + c4);
        }
    };

    float acc[MI][4][4];
    #pragma unroll
    for (int i = 0; i < MI; i++)
        #pragma unroll
        for (int j = 0; j < 4; j++)
            #pragma unroll
            for (int k = 0; k < 4; k++) acc[i][j][k] = 0.f;

    // prologue: stages 0..S-2
    #pragma unroll
    for (int k = 0; k < S - 1; k++) {
        if (k < nIter) issue(k);
        cp_commit();
    }

    for (int k = 0; k < nIter; k++) {
        cp_wait<S - 2>();
        __syncthreads();
        // issue next tile (slot being overwritten was consumed in iter k-1,
        // and all warps have passed the barrier above)
        if (k + S - 1 < nIter) issue(k + S - 1);
        cp_commit();

        const float* As = smem + (k % S) * STG;
        const float* Bs = As + AST;

        #pragma unroll
        for (int ks = 0; ks < 4; ks++) {
            unsigned af[MI][4], bf[4][2];
            #pragma unroll
            for (int mi = 0; mi < MI; mi++) {
                int r0 = (warpRow + mi * 16 + gid) * LDS_ + ks * 8 + tig;
                af[mi][0] = __float_as_uint(As[r0]);
                af[mi][1] = __float_as_uint(As[r0 + 8 * LDS_]);
                af[mi][2] = __float_as_uint(As[r0 + 4]);
                af[mi][3] = __float_as_uint(As[r0 + 8 * LDS_ + 4]);
            }
            #pragma unroll
            for (int ni = 0; ni < 4; ni++) {
                int r0 = (warpCol + ni * 8 + gid) * LDS_ + ks * 8 + tig;
                bf[ni][0] = __float_as_uint(Bs[r0]);
                bf[ni][1] = __float_as_uint(Bs[r0 + 4]);
            }
            #pragma unroll
            for (int mi = 0; mi < MI; mi++)
                #pragma unroll
                for (int ni = 0; ni < 4; ni++) {
                    asm volatile(
                        "mma.sync.aligned.m16n8k8.row.col.f32.tf32.tf32.f32 "
                        "{%0,%1,%2,%3}, {%4,%5,%6,%7}, {%8,%9}, {%0,%1,%2,%3};"
                        : "+f"(acc[mi][ni][0]), "+f"(acc[mi][ni][1]),
                          "+f"(acc[mi][ni][2]), "+f"(acc[mi][ni][3])
                        : "r"(af[mi][0]), "r"(af[mi][1]),
                          "r"(af[mi][2]), "r"(af[mi][3]),
                          "r"(bf[ni][0]), "r"(bf[ni][1]));
                }
        }
    }

    // ---- epilogue: +bias, optional tf32 rounding, float2 stores ----
    #pragma unroll
    for (int mi = 0; mi < MI; mi++) {
        size_t row = mBase + warpRow + mi * 16 + gid;
        #pragma unroll
        for (int ni = 0; ni < 4; ni++) {
            size_t col = nBase + warpCol + ni * 8 + tig * 2;
            float b0 = 0.f, b1 = 0.f;
            if (bias) { b0 = __ldg(bias + col); b1 = __ldg(bias + col + 1); }
            float2 v0, v1;
            v0.x = acc[mi][ni][0] + b0; v0.y = acc[mi][ni][1] + b1;
            v1.x = acc[mi][ni][2] + b0; v1.y = acc[mi][ni][3] + b1;
            if (round_out) {
                v0.x = f2tf(v0.x); v0.y = f2tf(v0.y);
                v1.x = f2tf(v1.x); v1.y = f2tf(v1.y);
            }
            *reinterpret_cast<float2*>(C + row * (size_t)ldc + col)       = v0;
            *reinterpret_cast<float2*>(C + (row + 8) * (size_t)ldc + col) = v1;
        }
    }
}

extern "C" void kernel_launch(void* const* d_in, const int* in_sizes, int n_in,
                              void* d_out, int out_size) {
    const float* x      = (const float*)d_in[0];  // [4,2048,4096]
    const float* lora_A = (const float*)d_in[1];  // [8,16,4096]
    const float* lora_B = (const float*)d_in[2];  // [8,4096,16]
    const float* W      = (const float*)d_in[3];  // [4096,4096]
    const float* bias   = (const float*)d_in[4];  // [4096]
    const float* lw     = (const float*)d_in[5];  // [8]
    float* out = (float*)d_out;                   // [8192,4096] fp32

    float *xr, *Wr, *Ar, *hbuf, *bcb;
    cudaGetSymbolAddress((void**)&xr,   g_x);
    cudaGetSymbolAddress((void**)&Wr,   g_W);
    cudaGetSymbolAddress((void**)&Ar,   g_A);
    cudaGetSymbolAddress((void**)&hbuf, g_h);
    cudaGetSymbolAddress((void**)&bcb,  g_Bc);

    // 0) tf32-RNA pre-rounding (cp.async copies raw bytes; round first)
    round_tf32_kernel<<<4096, 256>>>((const float4*)x, (float4*)xr, MTOT * DIN / 4);
    round_tf32_kernel<<<4096, 256>>>((const float4*)W, (float4*)Wr, DOUT * DIN / 4);
    round_tf32_kernel<<<512,  256>>>((const float4*)lora_A, (float4*)Ar, NR * DIN / 4);
    build_bc_kernel<<<(DOUT * NR + 255) / 256, 256>>>(lora_B, lw);

    constexpr int SMEM128 = 3 * (128 + 128) * 36 * 4;   // 110,592 B
    constexpr int SMEM64  = 3 * (64  + 128) * 36 * 4;   //  82,944 B
    cudaFuncSetAttribute(gemm_tf32_pipe<128>,
                         cudaFuncAttributeMaxDynamicSharedMemorySize, SMEM128);
    cudaFuncSetAttribute(gemm_tf32_pipe<64>,
                         cudaFuncAttributeMaxDynamicSharedMemorySize, SMEM64);

    // 1) h = x @ A_flat^T : [8192,128], K=4096  (h tf32-rounded at store)
    gemm_tf32_pipe<64><<<dim3(1, MTOT / 64), 256, SMEM64>>>(
        xr, DIN, Ar, DIN, DIN,
        nullptr, nullptr, 0,
        nullptr, hbuf, NR, 1);

    // 2) out = x @ W^T + h @ Bc^T + bias : [8192,4096]
    gemm_tf32_pipe<128><<<dim3(DOUT / 128, MTOT / 128), 256, SMEM128>>>(
        xr, DIN, Wr, DIN, DIN,
        hbuf, bcb, NR,
        bias, out, DOUT, 0);
}

// round 4
// speedup vs baseline: 2.0035x; 1.9738x over previous
#include <cuda_runtime.h>
#include <cuda_fp16.h>
#include <cstdint>

#define MTOT 8192      // B*S
#define DIN  4096
#define DOUT 4096
#define RANK 16
#define NR   128       // N_adapters * RANK
#define LORA_SCALE 2.0f

// ---- scratch (__device__ globals per allocation rules) ----
__device__ __half g_xh[MTOT * DIN];   // fp16 x     (64 MB)
__device__ __half g_Wh[DOUT * DIN];   // fp16 W     (32 MB)
__device__ __half g_Ah[NR * DIN];     // fp16 lora_A
__device__ __half g_hh[MTOT * NR];    // fp16 low-rank acts
__device__ __half g_Bch[DOUT * NR];   // fp16 coef-fused lora_B

__device__ __forceinline__ uint32_t s2u(const void* p) {
    return (uint32_t)__cvta_generic_to_shared(p);
}
__device__ __forceinline__ void cp16(uint32_t dst, const void* src) {
    asm volatile("cp.async.cg.shared.global [%0], [%1], 16;\n"
                 :: "r"(dst), "l"(src));
}
__device__ __forceinline__ void cp_commit() {
    asm volatile("cp.async.commit_group;" ::: "memory");
}
template<int N>
__device__ __forceinline__ void cp_wait() {
    asm volatile("cp.async.wait_group %0;" :: "n"(N) : "memory");
}

// ---- fp32 -> fp16 conversion, 8 elems/thread-iter ----
__global__ void f2h_kernel(const float4* __restrict__ in,
                           uint2* __restrict__ out, int n4) {
    for (int i = blockIdx.x * blockDim.x + threadIdx.x; i < n4;
         i += gridDim.x * blockDim.x) {
        float4 v = in[i];
        __half2 h0 = __floats2half2_rn(v.x, v.y);
        __half2 h1 = __floats2half2_rn(v.z, v.w);
        uint2 o;
        o.x = *reinterpret_cast<unsigned*>(&h0);
        o.y = *reinterpret_cast<unsigned*>(&h1);
        out[i] = o;
    }
}

// Bc[o][n*16+r] = fp16(SCALE * lw[n] * lora_B[n][o][r])
__global__ void build_bc_kernel(const float* __restrict__ lora_B,
                                const float* __restrict__ lw) {
    int idx = blockIdx.x * blockDim.x + threadIdx.x;
    if (idx >= DOUT * NR) return;
    int o  = idx / NR;
    int nr = idx - o * NR;
    int n  = nr >> 4;
    int r  = nr & 15;
    g_Bch[idx] = __float2half_rn(
        (LORA_SCALE * lw[n]) * lora_B[((size_t)n * DOUT + o) * RANK + r]);
}

// ============================================================================
// mma.sync fp16 (m16n8k16, fp32 accum) GEMM, 3-stage cp.async pipeline.
// BMx128 tile, BK=32, 256 threads (warps 2x4, warp tile (BM/2)x32).
// C[M,N] = A1[M,K1]@B1[N,K1]^T (+ A2[M,K2]@B2[N,K2]^T, ld=NR) (+ bias)
// HOUT: store fp16 (for h scratch); else fp32 (+bias).
// ============================================================================
template<int BM, bool HOUT>
__global__ __launch_bounds__(256, 2)
void gemm_f16_pipe(const __half* __restrict__ A1, int lda1,
                   const __half* __restrict__ B1, int ldb1, int K1,
                   const __half* __restrict__ A2, const __half* __restrict__ B2,
                   int K2,
                   const float* __restrict__ bias,
                   void* __restrict__ Cv, int ldc)
{
    constexpr int BN   = 128;
    constexpr int S    = 3;                       // pipeline stages
    constexpr int MI   = BM / 32;                 // 16-row mma tiles per warp
    constexpr int LDS_ = 40;                      // padded lead (halfs) -> 80B
    constexpr int AST  = BM * LDS_;               // A stage (halfs)
    constexpr int BST  = BN * LDS_;
    constexpr int STG  = AST + BST;

    extern __shared__ __half smem[];              // S * STG halfs

    const int tid    = threadIdx.x;
    const int wid    = tid >> 5;
    const int lane   = tid & 31;
    const int gid    = lane >> 2;
    const int tig    = lane & 3;
    const int warp_m = wid >> 2;                  // 0..1
    const int warp_n = wid & 3;                   // 0..3
    const int warpRow = warp_m * (BM / 2);
    const int warpCol = warp_n * 32;

    const size_t mBase = (size_t)blockIdx.y * BM;
    const size_t nBase = (size_t)blockIdx.x * BN;

    const int n1    = K1 / 32;
    const int nIter = n1 + K2 / 32;

    const uint32_t smemB = s2u(smem);

    auto issue = [&](int k) {
        int slot = k % S;
        uint32_t aS = smemB + slot * STG * 2;
        uint32_t bS = aS + AST * 2;
        const __half *Ap, *Bp; int ldA, ldB, kk;
        if (k < n1) { Ap = A1; Bp = B1; ldA = lda1; ldB = ldb1; kk = k * 32; }
        else        { Ap = A2; Bp = B2; ldA = NR;   ldB = NR;   kk = (k - n1) * 32; }
        // A: BM rows x 32 halfs = BM*4 16B-chunks
        #pragma unroll
        for (int i = 0; i < (BM * 4) / 256; i++) {
            int idx = tid + i * 256, row = idx >> 2, c8 = (idx & 3) << 3;
            cp16(aS + (row * LDS_ + c8) * 2,
                 Ap + (mBase + row) * (size_t)ldA + kk + c8);
        }
        // B: 128 rows x 32 halfs = 512 chunks
        #pragma unroll
        for (int i = 0; i < 2; i++) {
            int idx = tid + i * 256, row = idx >> 2, c8 = (idx & 3) << 3;
            cp16(bS + (row * LDS_ + c8) * 2,
                 Bp + (nBase + row) * (size_t)ldB + kk + c8);
        }
    };

    float acc[MI][4][4];
    #pragma unroll
    for (int i = 0; i < MI; i++)
        #pragma unroll
        for (int j = 0; j < 4; j++)
            #pragma unroll
            for (int k = 0; k < 4; k++) acc[i][j][k] = 0.f;

    #pragma unroll
    for (int k = 0; k < S - 1; k++) {
        if (k < nIter) issue(k);
        cp_commit();
    }

    for (int k = 0; k < nIter; k++) {
        cp_wait<S - 2>();
        __syncthreads();
        if (k + S - 1 < nIter) issue(k + S - 1);
        cp_commit();

        const __half* As = smem + (k % S) * STG;
        const __half* Bs = As + AST;

        #pragma unroll
        for (int ks = 0; ks < 2; ks++) {              // two k16 steps per BK=32
            const int k0 = ks * 16;
            unsigned af[MI][4], bf[4][2];
            #pragma unroll
            for (int mi = 0; mi < MI; mi++) {
                const __half* a = As + (warpRow + mi * 16 + gid) * LDS_ + k0 + 2 * tig;
                af[mi][0] = *reinterpret_cast<const unsigned*>(a);
                af[mi][1] = *reinterpret_cast<const unsigned*>(a + 8 * LDS_);
                af[mi][2] = *reinterpret_cast<const unsigned*>(a + 8);
                af[mi][3] = *reinterpret_cast<const unsigned*>(a + 8 * LDS_ + 8);
            }
            #pragma unroll
            for (int ni = 0; ni < 4; ni++) {
                const __half* b = Bs + (warpCol + ni * 8 + gid) * LDS_ + k0 + 2 * tig;
                bf[ni][0] = *reinterpret_cast<const unsigned*>(b);
                bf[ni][1] = *reinterpret_cast<const unsigned*>(b + 8);
            }
            #pragma unroll
            for (int mi = 0; mi < MI; mi++)
                #pragma unroll
                for (int ni = 0; ni < 4; ni++) {
                    asm volatile(
                        "mma.sync.aligned.m16n8k16.row.col.f32.f16.f16.f32 "
                        "{%0,%1,%2,%3}, {%4,%5,%6,%7}, {%8,%9}, {%0,%1,%2,%3};"
                        : "+f"(acc[mi][ni][0]), "+f"(acc[mi][ni][1]),
                          "+f"(acc[mi][ni][2]), "+f"(acc[mi][ni][3])
                        : "r"(af[mi][0]), "r"(af[mi][1]),
                          "r"(af[mi][2]), "r"(af[mi][3]),
                          "r"(bf[ni][0]), "r"(bf[ni][1]));
                }
        }
    }

    // ---- epilogue ----
    #pragma unroll
    for (int mi = 0; mi < MI; mi++) {
        size_t row = mBase + warpRow + mi * 16 + gid;
        #pragma unroll
        for (int ni = 0; ni < 4; ni++) {
            size_t col = nBase + warpCol + ni * 8 + tig * 2;
            if (HOUT) {
                __half* C = (__half*)Cv;
                __half2 v0 = __floats2half2_rn(acc[mi][ni][0], acc[mi][ni][1]);
                __half2 v1 = __floats2half2_rn(acc[mi][ni][2], acc[mi][ni][3]);
                *reinterpret_cast<__half2*>(C + row * (size_t)ldc + col)       = v0;
                *reinterpret_cast<__half2*>(C + (row + 8) * (size_t)ldc + col) = v1;
            } else {
                float* C = (float*)Cv;
                float b0 = 0.f, b1 = 0.f;
                if (bias) { b0 = __ldg(bias + col); b1 = __ldg(bias + col + 1); }
                float2 v0, v1;
                v0.x = acc[mi][ni][0] + b0; v0.y = acc[mi][ni][1] + b1;
                v1.x = acc[mi][ni][2] + b0; v1.y = acc[mi][ni][3] + b1;
                *reinterpret_cast<float2*>(C + row * (size_t)ldc + col)       = v0;
                *reinterpret_cast<float2*>(C + (row + 8) * (size_t)ldc + col) = v1;
            }
        }
    }
}

extern "C" void kernel_launch(void* const* d_in, const int* in_sizes, int n_in,
                              void* d_out, int out_size) {
    const float* x      = (const float*)d_in[0];  // [4,2048,4096]
    const float* lora_A = (const float*)d_in[1];  // [8,16,4096]
    const float* lora_B = (const float*)d_in[2];  // [8,4096,16]
    const float* W      = (const float*)d_in[3];  // [4096,4096]
    const float* bias   = (const float*)d_in[4];  // [4096]
    const float* lw     = (const float*)d_in[5];  // [8]
    float* out = (float*)d_out;                   // [8192,4096] fp32

    __half *xh, *Wh, *Ah, *hh, *bch;
    cudaGetSymbolAddress((void**)&xh,  g_xh);
    cudaGetSymbolAddress((void**)&Wh,  g_Wh);
    cudaGetSymbolAddress((void**)&Ah,  g_Ah);
    cudaGetSymbolAddress((void**)&hh,  g_hh);
    cudaGetSymbolAddress((void**)&bch, g_Bch);

    // 0) fp32 -> fp16 conversions (rn)
    f2h_kernel<<<4096, 256>>>((const float4*)x, (uint2*)xh, MTOT * DIN / 4);
    f2h_kernel<<<4096, 256>>>((const float4*)W, (uint2*)Wh, DOUT * DIN / 4);
    f2h_kernel<<<512,  256>>>((const float4*)lora_A, (uint2*)Ah, NR * DIN / 4);
    build_bc_kernel<<<(DOUT * NR + 255) / 256, 256>>>(lora_B, lw);

    constexpr int SMEM128 = 3 * (128 + 128) * 40 * 2;   // 61,440 B
    constexpr int SMEM64  = 3 * (64  + 128) * 40 * 2;   // 46,080 B
    cudaFuncSetAttribute(gemm_f16_pipe<128, false>,
                         cudaFuncAttributeMaxDynamicSharedMemorySize, SMEM128);
    cudaFuncSetAttribute(gemm_f16_pipe<64, true>,
                         cudaFuncAttributeMaxDynamicSharedMemorySize, SMEM64);

    // 1) h = x @ A_flat^T : [8192,128] fp16, K=4096
    gemm_f16_pipe<64, true><<<dim3(1, MTOT / 64), 256, SMEM64>>>(
        xh, DIN, Ah, DIN, DIN,
        nullptr, nullptr, 0,
        nullptr, hh, NR);

    // 2) out = x @ W^T + h @ Bc^T + bias : [8192,4096] fp32
    gemm_f16_pipe<128, false><<<dim3(DOUT / 128, MTOT / 128), 256, SMEM128>>>(
        xh, DIN, Wh, DIN, DIN,
        hh, bch, NR,
        bias, out, DOUT);
}

// round 5
// speedup vs baseline: 2.4286x; 1.2121x over previous
#include <cuda_runtime.h>
#include <cuda_fp16.h>
#include <cstdint>

#define MTOT 8192      // B*S
#define DIN  4096
#define DOUT 4096
#define RANK 16
#define NR   128       // N_adapters * RANK
#define LORA_SCALE 2.0f

// ---- scratch (__device__ globals per allocation rules) ----
__device__ __half g_xh[MTOT * DIN];   // fp16 x     (64 MB)
__device__ __half g_Wh[DOUT * DIN];   // fp16 W     (32 MB)
__device__ __half g_Ah[NR * DIN];     // fp16 lora_A
__device__ __half g_hh[MTOT * NR];    // fp16 low-rank acts
__device__ __half g_Bch[DOUT * NR];   // fp16 coef-fused lora_B

__device__ __forceinline__ uint32_t s2u(const void* p) {
    return (uint32_t)__cvta_generic_to_shared(p);
}
__device__ __forceinline__ void cp16(uint32_t dst, const void* src) {
    asm volatile("cp.async.cg.shared.global [%0], [%1], 16;\n"
                 :: "r"(dst), "l"(src));
}
__device__ __forceinline__ void cp_commit() {
    asm volatile("cp.async.commit_group;" ::: "memory");
}
template<int N>
__device__ __forceinline__ void cp_wait() {
    asm volatile("cp.async.wait_group %0;" :: "n"(N) : "memory");
}
// SW64 swizzle: conflict-free for 64B rows (cp.async stores + ldmatrix loads)
__device__ __forceinline__ uint32_t swz64(uint32_t b) {
    return b ^ ((b >> 3) & 0x30);
}
__device__ __forceinline__ void ldsm_x4(uint32_t& r0, uint32_t& r1,
                                        uint32_t& r2, uint32_t& r3, uint32_t a) {
    asm volatile("ldmatrix.sync.aligned.m8n8.x4.shared.b16 {%0,%1,%2,%3}, [%4];"
                 : "=r"(r0), "=r"(r1), "=r"(r2), "=r"(r3) : "r"(a));
}

// ---- fp32 -> fp16 conversion ----
__global__ void f2h_kernel(const float4* __restrict__ in,
                           uint2* __restrict__ out, int n4) {
    for (int i = blockIdx.x * blockDim.x + threadIdx.x; i < n4;
         i += gridDim.x * blockDim.x) {
        float4 v = in[i];
        __half2 h0 = __floats2half2_rn(v.x, v.y);
        __half2 h1 = __floats2half2_rn(v.z, v.w);
        uint2 o;
        o.x = *reinterpret_cast<unsigned*>(&h0);
        o.y = *reinterpret_cast<unsigned*>(&h1);
        out[i] = o;
    }
}

// Bc[o][n*16+r] = fp16(SCALE * lw[n] * lora_B[n][o][r])
__global__ void build_bc_kernel(const float* __restrict__ lora_B,
                                const float* __restrict__ lw) {
    int idx = blockIdx.x * blockDim.x + threadIdx.x;
    if (idx >= DOUT * NR) return;
    int o  = idx / NR;
    int nr = idx - o * NR;
    int n  = nr >> 4;
    int r  = nr & 15;
    g_Bch[idx] = __float2half_rn(
        (LORA_SCALE * lw[n]) * lora_B[((size_t)n * DOUT + o) * RANK + r]);
}

// ============================================================================
// GEMM1 kernel (round-4 proven): fp16 mma, BMx128, BK=32, padded smem.
// ============================================================================
template<int BM, bool HOUT>
__global__ __launch_bounds__(256, 2)
void gemm_f16_pipe(const __half* __restrict__ A1, int lda1,
                   const __half* __restrict__ B1, int ldb1, int K1,
                   const float* __restrict__ bias,
                   void* __restrict__ Cv, int ldc)
{
    constexpr int BN   = 128;
    constexpr int S    = 3;
    constexpr int MI   = BM / 32;
    constexpr int LDS_ = 40;
    constexpr int AST  = BM * LDS_;
    constexpr int BST  = BN * LDS_;
    constexpr int STG  = AST + BST;

    extern __shared__ __half smem[];

    const int tid    = threadIdx.x;
    const int wid    = tid >> 5;
    const int lane   = tid & 31;
    const int gid    = lane >> 2;
    const int tig    = lane & 3;
    const int warpRow = (wid >> 2) * (BM / 2);
    const int warpCol = (wid & 3) * 32;

    const size_t mBase = (size_t)blockIdx.y * BM;
    const size_t nBase = (size_t)blockIdx.x * BN;
    const int nIter = K1 / 32;
    const uint32_t smemB = s2u(smem);

    auto issue = [&](int k) {
        int slot = k % S;
        uint32_t aS = smemB + slot * STG * 2;
        uint32_t bS = aS + AST * 2;
        int kk = k * 32;
        #pragma unroll
        for (int i = 0; i < (BM * 4) / 256; i++) {
            int idx = tid + i * 256, row = idx >> 2, c8 = (idx & 3) << 3;
            cp16(aS + (row * LDS_ + c8) * 2,
                 A1 + (mBase + row) * (size_t)lda1 + kk + c8);
        }
        #pragma unroll
        for (int i = 0; i < 2; i++) {
            int idx = tid + i * 256, row = idx >> 2, c8 = (idx & 3) << 3;
            cp16(bS + (row * LDS_ + c8) * 2,
                 B1 + (nBase + row) * (size_t)ldb1 + kk + c8);
        }
    };

    float acc[MI][4][4];
    #pragma unroll
    for (int i = 0; i < MI; i++)
        #pragma unroll
        for (int j = 0; j < 4; j++)
            #pragma unroll
            for (int k = 0; k < 4; k++) acc[i][j][k] = 0.f;

    #pragma unroll
    for (int k = 0; k < S - 1; k++) { if (k < nIter) issue(k); cp_commit(); }

    for (int k = 0; k < nIter; k++) {
        cp_wait<S - 2>();
        __syncthreads();
        if (k + S - 1 < nIter) issue(k + S - 1);
        cp_commit();

        const __half* As = smem + (k % S) * STG;
        const __half* Bs = As + AST;

        #pragma unroll
        for (int ks = 0; ks < 2; ks++) {
            const int k0 = ks * 16;
            unsigned af[MI][4], bf[4][2];
            #pragma unroll
            for (int mi = 0; mi < MI; mi++) {
                const __half* a = As + (warpRow + mi * 16 + gid) * LDS_ + k0 + 2 * tig;
                af[mi][0] = *reinterpret_cast<const unsigned*>(a);
                af[mi][1] = *reinterpret_cast<const unsigned*>(a + 8 * LDS_);
                af[mi][2] = *reinterpret_cast<const unsigned*>(a + 8);
                af[mi][3] = *reinterpret_cast<const unsigned*>(a + 8 * LDS_ + 8);
            }
            #pragma unroll
            for (int ni = 0; ni < 4; ni++) {
                const __half* b = Bs + (warpCol + ni * 8 + gid) * LDS_ + k0 + 2 * tig;
                bf[ni][0] = *reinterpret_cast<const unsigned*>(b);
                bf[ni][1] = *reinterpret_cast<const unsigned*>(b + 8);
            }
            #pragma unroll
            for (int mi = 0; mi < MI; mi++)
                #pragma unroll
                for (int ni = 0; ni < 4; ni++) {
                    asm volatile(
                        "mma.sync.aligned.m16n8k16.row.col.f32.f16.f16.f32 "
                        "{%0,%1,%2,%3}, {%4,%5,%6,%7}, {%8,%9}, {%0,%1,%2,%3};"
                        : "+f"(acc[mi][ni][0]), "+f"(acc[mi][ni][1]),
                          "+f"(acc[mi][ni][2]), "+f"(acc[mi][ni][3])
                        : "r"(af[mi][0]), "r"(af[mi][1]),
                          "r"(af[mi][2]), "r"(af[mi][3]),
                          "r"(bf[ni][0]), "r"(bf[ni][1]));
                }
        }
    }

    #pragma unroll
    for (int mi = 0; mi < MI; mi++) {
        size_t row = mBase + warpRow + mi * 16 + gid;
        #pragma unroll
        for (int ni = 0; ni < 4; ni++) {
            size_t col = nBase + warpCol + ni * 8 + tig * 2;
            if (HOUT) {
                __half* C = (__half*)Cv;
                __half2 v0 = __floats2half2_rn(acc[mi][ni][0], acc[mi][ni][1]);
                __half2 v1 = __floats2half2_rn(acc[mi][ni][2], acc[mi][ni][3]);
                *reinterpret_cast<__half2*>(C + row * (size_t)ldc + col)       = v0;
                *reinterpret_cast<__half2*>(C + (row + 8) * (size_t)ldc + col) = v1;
            } else {
                float* C = (float*)Cv;
                float b0 = 0.f, b1 = 0.f;
                if (bias) { b0 = __ldg(bias + col); b1 = __ldg(bias + col + 1); }
                float2 v0, v1;
                v0.x = acc[mi][ni][0] + b0; v0.y = acc[mi][ni][1] + b1;
                v1.x = acc[mi][ni][2] + b0; v1.y = acc[mi][ni][3] + b1;
                *reinterpret_cast<float2*>(C + row * (size_t)ldc + col)       = v0;
                *reinterpret_cast<float2*>(C + (row + 8) * (size_t)ldc + col) = v1;
            }
        }
    }
}

// ============================================================================
// Main GEMM: 128x256 tile, BK=32, 512 threads (warps 2x8, warp tile 64x32),
// ldmatrix fragments, SW64 swizzle, 3-stage cp.async pipeline.
// C = A1[M,K1]@B1[N,K1]^T + A2[M,K2]@B2[N,K2]^T (ld=NR) + bias
// ============================================================================
__global__ __launch_bounds__(512, 1)
void gemm_f16_big(const __half* __restrict__ A1, int lda1,
                  const __half* __restrict__ B1, int ldb1, int K1,
                  const __half* __restrict__ A2, const __half* __restrict__ B2,
                  int K2,
                  const float* __restrict__ bias,
                  float* __restrict__ C, int ldc)
{
    constexpr int BM = 128, BN = 256;
    constexpr int S  = 3;
    constexpr int AST = BM * 64;              // A stage bytes (64B per row)
    constexpr int STG = (BM + BN) * 64;       // 24576 B per stage
    constexpr int MI = 4, NI = 4;             // warp tile 64x32

    extern __shared__ __half smem[];

    const int tid  = threadIdx.x;
    const int wid  = tid >> 5;
    const int lane = tid & 31;
    const int gid  = lane >> 2;
    const int tig  = lane & 3;
    const int warpRow = (wid & 1) * 64;       // 2 warps in M
    const int warpCol = (wid >> 1) * 32;      // 8 warps in N

    const size_t mBase = (size_t)blockIdx.y * BM;
    const size_t nBase = (size_t)blockIdx.x * BN;

    const int n1    = K1 / 32;
    const int nIter = n1 + K2 / 32;
    const uint32_t tiles = s2u(smem);

    // ---- per-lane ldmatrix base offsets (swizzled, within-stage) ----
    const int quad = lane >> 3, l8 = lane & 7;
    // A x4: quads -> (m +0/+8, kbyte 0/16)
    const uint32_t aoff0 =
        swz64((uint32_t)((warpRow + ((quad & 1) << 3) + l8) * 64 + ((quad >> 1) << 4)));
    // B x4: quads -> (n +0/+8, kbyte 0/16); B region starts at AST
    const uint32_t boff0 =
        swz64((uint32_t)(AST + (warpCol + ((quad >> 1) << 3) + l8) * 64 + ((quad & 1) << 4)));

    auto issue = [&](int k) {
        int slot = k % S;
        uint32_t base = tiles + slot * STG;
        const __half *Ap, *Bp; int ldA, ldB, kk;
        if (k < n1) { Ap = A1; Bp = B1; ldA = lda1; ldB = ldb1; kk = k * 32; }
        else        { Ap = A2; Bp = B2; ldA = NR;   ldB = NR;   kk = (k - n1) * 32; }
        // A: 128 rows x 4 chunks = 512 (1/thread)
        {
            int row = tid >> 2, c8 = (tid & 3) << 3;
            cp16(base + swz64(row * 64 + c8 * 2),
                 Ap + (mBase + row) * (size_t)ldA + kk + c8);
        }
        // B: 256 rows x 4 chunks = 1024 (2/thread)
        #pragma unroll
        for (int i = 0; i < 2; i++) {
            int idx = tid + i * 512, row = idx >> 2, c8 = (idx & 3) << 3;
            cp16(base + swz64(AST + row * 64 + c8 * 2),
                 Bp + (nBase + row) * (size_t)ldB + kk + c8);
        }
    };

    float acc[MI][NI][4];
    #pragma unroll
    for (int i = 0; i < MI; i++)
        #pragma unroll
        for (int j = 0; j < NI; j++)
            #pragma unroll
            for (int k = 0; k < 4; k++) acc[i][j][k] = 0.f;

    #pragma unroll
    for (int k = 0; k < S - 1; k++) { if (k < nIter) issue(k); cp_commit(); }

    for (int k = 0; k < nIter; k++) {
        cp_wait<S - 2>();
        __syncthreads();
        if (k + S - 1 < nIter) issue(k + S - 1);
        cp_commit();

        const uint32_t sbase = tiles + (k % S) * STG;

        #pragma unroll
        for (int ks = 0; ks < 2; ks++) {
            const uint32_t kx = ks << 5;               // XOR 32 bytes (safe w/ SW64)
            unsigned af[MI][4], bg[NI / 2][4];
            #pragma unroll
            for (int mi = 0; mi < MI; mi++)
                ldsm_x4(af[mi][0], af[mi][1], af[mi][2], af[mi][3],
                        (sbase + aoff0 + mi * 1024) ^ kx);
            #pragma unroll
            for (int g = 0; g < NI / 2; g++)
                ldsm_x4(bg[g][0], bg[g][1], bg[g][2], bg[g][3],
                        (sbase + boff0 + g * 1024) ^ kx);
            #pragma unroll
            for (int mi = 0; mi < MI; mi++)
                #pragma unroll
                for (int ni = 0; ni < NI; ni++) {
                    unsigned b0 = bg[ni >> 1][(ni & 1) * 2];
                    unsigned b1 = bg[ni >> 1][(ni & 1) * 2 + 1];
                    asm volatile(
                        "mma.sync.aligned.m16n8k16.row.col.f32.f16.f16.f32 "
                        "{%0,%1,%2,%3}, {%4,%5,%6,%7}, {%8,%9}, {%0,%1,%2,%3};"
                        : "+f"(acc[mi][ni][0]), "+f"(acc[mi][ni][1]),
                          "+f"(acc[mi][ni][2]), "+f"(acc[mi][ni][3])
                        : "r"(af[mi][0]), "r"(af[mi][1]),
                          "r"(af[mi][2]), "r"(af[mi][3]),
                          "r"(b0), "r"(b1));
                }
        }
    }

    // ---- epilogue: +bias, float2 stores ----
    #pragma unroll
    for (int mi = 0; mi < MI; mi++) {
        size_t row = mBase + warpRow + mi * 16 + gid;
        #pragma unroll
        for (int ni = 0; ni < NI; ni++) {
            size_t col = nBase + warpCol + ni * 8 + tig * 2;
            float b0 = __ldg(bias + col);
            float b1 = __ldg(bias + col + 1);
            float2 v0, v1;
            v0.x = acc[mi][ni][0] + b0; v0.y = acc[mi][ni][1] + b1;
            v1.x = acc[mi][ni][2] + b0; v1.y = acc[mi][ni][3] + b1;
            *reinterpret_cast<float2*>(C + row * (size_t)ldc + col)       = v0;
            *reinterpret_cast<float2*>(C + (row + 8) * (size_t)ldc + col) = v1;
        }
    }
}

extern "C" void kernel_launch(void* const* d_in, const int* in_sizes, int n_in,
                              void* d_out, int out_size) {
    const float* x      = (const float*)d_in[0];
    const float* lora_A = (const float*)d_in[1];
    const float* lora_B = (const float*)d_in[2];
    const float* W      = (const float*)d_in[3];
    const float* bias   = (const float*)d_in[4];
    const float* lw     = (const float*)d_in[5];
    float* out = (float*)d_out;

    __half *xh, *Wh, *Ah, *hh, *bch;
    cudaGetSymbolAddress((void**)&xh,  g_xh);
    cudaGetSymbolAddress((void**)&Wh,  g_Wh);
    cudaGetSymbolAddress((void**)&Ah,  g_Ah);
    cudaGetSymbolAddress((void**)&hh,  g_hh);
    cudaGetSymbolAddress((void**)&bch, g_Bch);

    // 0) fp32 -> fp16 conversions
    f2h_kernel<<<4096, 256>>>((const float4*)x, (uint2*)xh, MTOT * DIN / 4);
    f2h_kernel<<<4096, 256>>>((const float4*)W, (uint2*)Wh, DOUT * DIN / 4);
    f2h_kernel<<<512,  256>>>((const float4*)lora_A, (uint2*)Ah, NR * DIN / 4);
    build_bc_kernel<<<(DOUT * NR + 255) / 256, 256>>>(lora_B, lw);

    constexpr int SMEM64  = 3 * (64 + 128) * 40 * 2;    // 46,080 B
    constexpr int SMEMBIG = 3 * (128 + 256) * 64;       // 73,728 B
    cudaFuncSetAttribute(gemm_f16_pipe<64, true>,
                         cudaFuncAttributeMaxDynamicSharedMemorySize, SMEM64);
    cudaFuncSetAttribute(gemm_f16_big,
                         cudaFuncAttributeMaxDynamicSharedMemorySize, SMEMBIG);

    // 1) h = x @ A_flat^T : [8192,128] fp16, K=4096
    gemm_f16_pipe<64, true><<<dim3(1, MTOT / 64), 256, SMEM64>>>(
        xh, DIN, Ah, DIN, DIN, nullptr, hh, NR);

    // 2) out = x @ W^T + h @ Bc^T + bias : [8192,4096] fp32
    gemm_f16_big<<<dim3(DOUT / 256, MTOT / 128), 512, SMEMBIG>>>(
        xh, DIN, Wh, DIN, DIN,
        hh, bch, NR,
        bias, out, DOUT);
}

// round 6
// speedup vs baseline: 2.4946x; 1.0272x over previous
#include <cuda_runtime.h>
#include <cuda_fp16.h>
#include <cstdint>

#define MTOT 8192      // B*S
#define DIN  4096
#define DOUT 4096
#define RANK 16
#define NR   128       // N_adapters * RANK
#define LORA_SCALE 2.0f

// ---- scratch (__device__ globals per allocation rules) ----
__device__ __half g_xh[MTOT * DIN];   // fp16 x
__device__ __half g_Wh[DOUT * DIN];   // fp16 W
__device__ __half g_Ah[NR * DIN];     // fp16 lora_A
__device__ __half g_hh[MTOT * NR];    // fp16 low-rank acts
__device__ __half g_Bch[DOUT * NR];   // fp16 coef-fused lora_B

__device__ __forceinline__ uint32_t s2u(const void* p) {
    return (uint32_t)__cvta_generic_to_shared(p);
}
__device__ __forceinline__ void cp16(uint32_t dst, const void* src) {
    asm volatile("cp.async.cg.shared.global [%0], [%1], 16;\n"
                 :: "r"(dst), "l"(src));
}
__device__ __forceinline__ void cp_commit() {
    asm volatile("cp.async.commit_group;" ::: "memory");
}
template<int N>
__device__ __forceinline__ void cp_wait() {
    asm volatile("cp.async.wait_group %0;" :: "n"(N) : "memory");
}
__device__ __forceinline__ uint32_t swz64(uint32_t b) {
    return b ^ ((b >> 3) & 0x30);
}
__device__ __forceinline__ void ldsm_x4(uint32_t& r0, uint32_t& r1,
                                        uint32_t& r2, uint32_t& r3, uint32_t a) {
    asm volatile("ldmatrix.sync.aligned.m8n8.x4.shared.b16 {%0,%1,%2,%3}, [%4];"
                 : "=r"(r0), "=r"(r1), "=r"(r2), "=r"(r3) : "r"(a));
}

// ---- fp32 -> fp16 conversion ----
__global__ void f2h_kernel(const float4* __restrict__ in,
                           uint2* __restrict__ out, int n4) {
    for (int i = blockIdx.x * blockDim.x + threadIdx.x; i < n4;
         i += gridDim.x * blockDim.x) {
        float4 v = in[i];
        __half2 h0 = __floats2half2_rn(v.x, v.y);
        __half2 h1 = __floats2half2_rn(v.z, v.w);
        uint2 o;
        o.x = *reinterpret_cast<unsigned*>(&h0);
        o.y = *reinterpret_cast<unsigned*>(&h1);
        out[i] = o;
    }
}

// Bc[o][n*16+r] = fp16(SCALE * lw[n] * lora_B[n][o][r])
__global__ void build_bc_kernel(const float* __restrict__ lora_B,
                                const float* __restrict__ lw) {
    int idx = blockIdx.x * blockDim.x + threadIdx.x;
    if (idx >= DOUT * NR) return;
    int o  = idx / NR;
    int nr = idx - o * NR;
    int n  = nr >> 4;
    int r  = nr & 15;
    g_Bch[idx] = __float2half_rn(
        (LORA_SCALE * lw[n]) * lora_B[((size_t)n * DOUT + o) * RANK + r]);
}

// ============================================================================
// GEMM1 (round-4 proven): fp16 mma, 64x128, BK=32, padded smem, 256 thr.
// ============================================================================
__global__ __launch_bounds__(256, 2)
void gemm1_f16(const __half* __restrict__ A1, int lda1,
               const __half* __restrict__ B1, int ldb1, int K1,
               __half* __restrict__ C, int ldc)
{
    constexpr int BM = 64, BN = 128;
    constexpr int S = 3;
    constexpr int MI = 2;
    constexpr int LDS_ = 40;
    constexpr int AST = BM * LDS_;
    constexpr int BST = BN * LDS_;
    constexpr int STG = AST + BST;

    extern __shared__ __half smem[];

    const int tid  = threadIdx.x;
    const int wid  = tid >> 5;
    const int lane = tid & 31;
    const int gid  = lane >> 2;
    const int tig  = lane & 3;
    const int warpRow = (wid >> 2) * 32;
    const int warpCol = (wid & 3) * 32;

    const size_t mBase = (size_t)blockIdx.y * BM;
    const int nIter = K1 / 32;
    const uint32_t smemB = s2u(smem);

    auto issue = [&](int k) {
        int slot = k % S;
        uint32_t aS = smemB + slot * STG * 2;
        uint32_t bS = aS + AST * 2;
        int kk = k * 32;
        {
            int idx = tid, row = idx >> 2, c8 = (idx & 3) << 3;
            cp16(aS + (row * LDS_ + c8) * 2,
                 A1 + (mBase + row) * (size_t)lda1 + kk + c8);
        }
        #pragma unroll
        for (int i = 0; i < 2; i++) {
            int idx = tid + i * 256, row = idx >> 2, c8 = (idx & 3) << 3;
            cp16(bS + (row * LDS_ + c8) * 2,
                 B1 + row * (size_t)ldb1 + kk + c8);
        }
    };

    float acc[MI][4][4];
    #pragma unroll
    for (int i = 0; i < MI; i++)
        #pragma unroll
        for (int j = 0; j < 4; j++)
            #pragma unroll
            for (int k = 0; k < 4; k++) acc[i][j][k] = 0.f;

    #pragma unroll
    for (int k = 0; k < S - 1; k++) { if (k < nIter) issue(k); cp_commit(); }

    for (int k = 0; k < nIter; k++) {
        cp_wait<S - 2>();
        __syncthreads();
        if (k + S - 1 < nIter) issue(k + S - 1);
        cp_commit();

        const __half* As = smem + (k % S) * STG;
        const __half* Bs = As + AST;

        #pragma unroll
        for (int ks = 0; ks < 2; ks++) {
            const int k0 = ks * 16;
            unsigned af[MI][4], bf[4][2];
            #pragma unroll
            for (int mi = 0; mi < MI; mi++) {
                const __half* a = As + (warpRow + mi * 16 + gid) * LDS_ + k0 + 2 * tig;
                af[mi][0] = *reinterpret_cast<const unsigned*>(a);
                af[mi][1] = *reinterpret_cast<const unsigned*>(a + 8 * LDS_);
                af[mi][2] = *reinterpret_cast<const unsigned*>(a + 8);
                af[mi][3] = *reinterpret_cast<const unsigned*>(a + 8 * LDS_ + 8);
            }
            #pragma unroll
            for (int ni = 0; ni < 4; ni++) {
                const __half* b = Bs + (warpCol + ni * 8 + gid) * LDS_ + k0 + 2 * tig;
                bf[ni][0] = *reinterpret_cast<const unsigned*>(b);
                bf[ni][1] = *reinterpret_cast<const unsigned*>(b + 8);
            }
            #pragma unroll
            for (int mi = 0; mi < MI; mi++)
                #pragma unroll
                for (int ni = 0; ni < 4; ni++) {
                    asm volatile(
                        "mma.sync.aligned.m16n8k16.row.col.f32.f16.f16.f32 "
                        "{%0,%1,%2,%3}, {%4,%5,%6,%7}, {%8,%9}, {%0,%1,%2,%3};"
                        : "+f"(acc[mi][ni][0]), "+f"(acc[mi][ni][1]),
                          "+f"(acc[mi][ni][2]), "+f"(acc[mi][ni][3])
                        : "r"(af[mi][0]), "r"(af[mi][1]),
                          "r"(af[mi][2]), "r"(af[mi][3]),
                          "r"(bf[ni][0]), "r"(bf[ni][1]));
                }
        }
    }

    #pragma unroll
    for (int mi = 0; mi < MI; mi++) {
        size_t row = mBase + warpRow + mi * 16 + gid;
        #pragma unroll
        for (int ni = 0; ni < 4; ni++) {
            size_t col = warpCol + ni * 8 + tig * 2;
            __half2 v0 = __floats2half2_rn(acc[mi][ni][0], acc[mi][ni][1]);
            __half2 v1 = __floats2half2_rn(acc[mi][ni][2], acc[mi][ni][3]);
            *reinterpret_cast<__half2*>(C + row * (size_t)ldc + col)       = v0;
            *reinterpret_cast<__half2*>(C + (row + 8) * (size_t)ldc + col) = v1;
        }
    }
}

// ============================================================================
// Main GEMM: 128x256 tile, BK=32, 256 threads (warps 2x4, warp tile 64x64),
// ldmatrix + SW64, 3-stage cp.async pipeline.
// C = A1[M,K1]@B1[N,K1]^T + A2[M,K2]@B2[N,K2]^T (ld=NR) + bias
// ============================================================================
__global__ __launch_bounds__(256, 1)
void gemm_f16_big(const __half* __restrict__ A1, int lda1,
                  const __half* __restrict__ B1, int ldb1, int K1,
                  const __half* __restrict__ A2, const __half* __restrict__ B2,
                  int K2,
                  const float* __restrict__ bias,
                  float* __restrict__ C, int ldc)
{
    constexpr int BM = 128, BN = 256;
    constexpr int S  = 3;
    constexpr int AST = BM * 64;              // A stage bytes
    constexpr int STG = (BM + BN) * 64;       // 24576 B per stage
    constexpr int MI = 4, NI = 8;             // warp tile 64x64

    extern __shared__ __half smem[];

    const int tid  = threadIdx.x;
    const int wid  = tid >> 5;
    const int lane = tid & 31;
    const int gid  = lane >> 2;
    const int tig  = lane & 3;
    const int warpRow = (wid & 1) * 64;       // 2 warps in M
    const int warpCol = (wid >> 1) * 64;      // 4 warps in N

    const size_t mBase = (size_t)blockIdx.y * BM;
    const size_t nBase = (size_t)blockIdx.x * BN;

    const int n1    = K1 / 32;
    const int nIter = n1 + K2 / 32;
    const uint32_t tiles = s2u(smem);

    // ---- per-lane ldmatrix base offsets (swizzled, within-stage) ----
    const int quad = lane >> 3, l8 = lane & 7;
    const uint32_t aoff0 =
        swz64((uint32_t)((warpRow + ((quad & 1) << 3) + l8) * 64 + ((quad >> 1) << 4)));
    const uint32_t boff0 =
        swz64((uint32_t)(AST + (warpCol + ((quad >> 1) << 3) + l8) * 64 + ((quad & 1) << 4)));

    auto issue = [&](int k) {
        int slot = k % S;
        uint32_t base = tiles + slot * STG;
        const __half *Ap, *Bp; int ldA, ldB, kk;
        if (k < n1) { Ap = A1; Bp = B1; ldA = lda1; ldB = ldb1; kk = k * 32; }
        else        { Ap = A2; Bp = B2; ldA = NR;   ldB = NR;   kk = (k - n1) * 32; }
        // A: 128 rows x 4 chunks = 512 (2/thread)
        #pragma unroll
        for (int i = 0; i < 2; i++) {
            int idx = tid + i * 256, row = idx >> 2, c8 = (idx & 3) << 3;
            cp16(base + swz64(row * 64 + c8 * 2),
                 Ap + (mBase + row) * (size_t)ldA + kk + c8);
        }
        // B: 256 rows x 4 chunks = 1024 (4/thread)
        #pragma unroll
        for (int i = 0; i < 4; i++) {
            int idx = tid + i * 256, row = idx >> 2, c8 = (idx & 3) << 3;
            cp16(base + swz64(AST + row * 64 + c8 * 2),
                 Bp + (nBase + row) * (size_t)ldB + kk + c8);
        }
    };

    float acc[MI][NI][4];
    #pragma unroll
    for (int i = 0; i < MI; i++)
        #pragma unroll
        for (int j = 0; j < NI; j++)
            #pragma unroll
            for (int k = 0; k < 4; k++) acc[i][j][k] = 0.f;

    #pragma unroll
    for (int k = 0; k < S - 1; k++) { if (k < nIter) issue(k); cp_commit(); }

    for (int k = 0; k < nIter; k++) {
        cp_wait<S - 2>();
        __syncthreads();
        if (k + S - 1 < nIter) issue(k + S - 1);
        cp_commit();

        const uint32_t sbase = tiles + (k % S) * STG;

        #pragma unroll
        for (int ks = 0; ks < 2; ks++) {
            const uint32_t kx = ks << 5;               // XOR 32 bytes (SW64-safe)
            unsigned af[MI][4], bg[NI / 2][4];
            #pragma unroll
            for (int mi = 0; mi < MI; mi++)
                ldsm_x4(af[mi][0], af[mi][1], af[mi][2], af[mi][3],
                        (sbase + aoff0 + mi * 1024) ^ kx);
            #pragma unroll
            for (int g = 0; g < NI / 2; g++)
                ldsm_x4(bg[g][0], bg[g][1], bg[g][2], bg[g][3],
                        (sbase + boff0 + g * 1024) ^ kx);
            #pragma unroll
            for (int mi = 0; mi < MI; mi++)
                #pragma unroll
                for (int ni = 0; ni < NI; ni++) {
                    unsigned b0 = bg[ni >> 1][(ni & 1) * 2];
                    unsigned b1 = bg[ni >> 1][(ni & 1) * 2 + 1];
                    asm volatile(
                        "mma.sync.aligned.m16n8k16.row.col.f32.f16.f16.f32 "
                        "{%0,%1,%2,%3}, {%4,%5,%6,%7}, {%8,%9}, {%0,%1,%2,%3};"
                        : "+f"(acc[mi][ni][0]), "+f"(acc[mi][ni][1]),
                          "+f"(acc[mi][ni][2]), "+f"(acc[mi][ni][3])
                        : "r"(af[mi][0]), "r"(af[mi][1]),
                          "r"(af[mi][2]), "r"(af[mi][3]),
                          "r"(b0), "r"(b1));
                }
        }
    }

    // ---- epilogue: +bias, float2 stores ----
    #pragma unroll
    for (int mi = 0; mi < MI; mi++) {
        size_t row = mBase + warpRow + mi * 16 + gid;
        #pragma unroll
        for (int ni = 0; ni < NI; ni++) {
            size_t col = nBase + warpCol + ni * 8 + tig * 2;
            float b0 = __ldg(bias + col);
            float b1 = __ldg(bias + col + 1);
            float2 v0, v1;
            v0.x = acc[mi][ni][0] + b0; v0.y = acc[mi][ni][1] + b1;
            v1.x = acc[mi][ni][2] + b0; v1.y = acc[mi][ni][3] + b1;
            *reinterpret_cast<float2*>(C + row * (size_t)ldc + col)       = v0;
            *reinterpret_cast<float2*>(C + (row + 8) * (size_t)ldc + col) = v1;
        }
    }
}

extern "C" void kernel_launch(void* const* d_in, const int* in_sizes, int n_in,
                              void* d_out, int out_size) {
    const float* x      = (const float*)d_in[0];
    const float* lora_A = (const float*)d_in[1];
    const float* lora_B = (const float*)d_in[2];
    const float* W      = (const float*)d_in[3];
    const float* bias   = (const float*)d_in[4];
    const float* lw     = (const float*)d_in[5];
    float* out = (float*)d_out;

    __half *xh, *Wh, *Ah, *hh, *bch;
    cudaGetSymbolAddress((void**)&xh,  g_xh);
    cudaGetSymbolAddress((void**)&Wh,  g_Wh);
    cudaGetSymbolAddress((void**)&Ah,  g_Ah);
    cudaGetSymbolAddress((void**)&hh,  g_hh);
    cudaGetSymbolAddress((void**)&bch, g_Bch);

    // 0) fp32 -> fp16 conversions
    f2h_kernel<<<4096, 256>>>((const float4*)x, (uint2*)xh, MTOT * DIN / 4);
    f2h_kernel<<<4096, 256>>>((const float4*)W, (uint2*)Wh, DOUT * DIN / 4);
    f2h_kernel<<<512,  256>>>((const float4*)lora_A, (uint2*)Ah, NR * DIN / 4);
    build_bc_kernel<<<(DOUT * NR + 255) / 256, 256>>>(lora_B, lw);

    constexpr int SMEM1   = 3 * (64 + 128) * 40 * 2;    // 46,080 B
    constexpr int SMEMBIG = 3 * (128 + 256) * 64;       // 73,728 B
    cudaFuncSetAttribute(gemm1_f16,
                         cudaFuncAttributeMaxDynamicSharedMemorySize, SMEM1);
    cudaFuncSetAttribute(gemm_f16_big,
                         cudaFuncAttributeMaxDynamicSharedMemorySize, SMEMBIG);

    // 1) h = x @ A_flat^T : [8192,128] fp16, K=4096
    gemm1_f16<<<dim3(1, MTOT / 64), 256, SMEM1>>>(
        xh, DIN, Ah, DIN, DIN, hh, NR);

    // 2) out = x @ W^T + h @ Bc^T + bias : [8192,4096] fp32
    gemm_f16_big<<<dim3(DOUT / 256, MTOT / 128), 256, SMEMBIG>>>(
        xh, DIN, Wh, DIN, DIN,
        hh, bch, NR,
        bias, out, DOUT);
}

// round 7
// speedup vs baseline: 2.8254x; 1.1326x over previous
#include <cuda_runtime.h>
#include <cuda_fp16.h>
#include <cstdint>

#define MTOT 8192      // B*S
#define DIN  4096
#define DOUT 4096
#define RANK 16
#define NR   128       // N_adapters * RANK
#define LORA_SCALE 2.0f

// ---- scratch (__device__ globals per allocation rules) ----
__device__ __half g_xh[MTOT * DIN];   // fp16 x
__device__ __half g_Wh[DOUT * DIN];   // fp16 W
__device__ __half g_Ah[NR * DIN];     // fp16 lora_A
__device__ __half g_hh[MTOT * NR];    // fp16 low-rank acts
__device__ __half g_Bch[DOUT * NR];   // fp16 coef-fused lora_B

__device__ __forceinline__ uint32_t s2u(const void* p) {
    return (uint32_t)__cvta_generic_to_shared(p);
}
__device__ __forceinline__ void cp16(uint32_t dst, const void* src) {
    asm volatile("cp.async.cg.shared.global [%0], [%1], 16;\n"
                 :: "r"(dst), "l"(src));
}
__device__ __forceinline__ void cp_commit() {
    asm volatile("cp.async.commit_group;" ::: "memory");
}
template<int N>
__device__ __forceinline__ void cp_wait() {
    asm volatile("cp.async.wait_group %0;" :: "n"(N) : "memory");
}
__device__ __forceinline__ void ldsm_x4(uint32_t& r0, uint32_t& r1,
                                        uint32_t& r2, uint32_t& r3, uint32_t a) {
    asm volatile("ldmatrix.sync.aligned.m8n8.x4.shared.b16 {%0,%1,%2,%3}, [%4];"
                 : "=r"(r0), "=r"(r1), "=r"(r2), "=r"(r3) : "r"(a));
}

// ---- fp32 -> fp16 conversion ----
__global__ void f2h_kernel(const float4* __restrict__ in,
                           uint2* __restrict__ out, int n4) {
    for (int i = blockIdx.x * blockDim.x + threadIdx.x; i < n4;
         i += gridDim.x * blockDim.x) {
        float4 v = in[i];
        __half2 h0 = __floats2half2_rn(v.x, v.y);
        __half2 h1 = __floats2half2_rn(v.z, v.w);
        uint2 o;
        o.x = *reinterpret_cast<unsigned*>(&h0);
        o.y = *reinterpret_cast<unsigned*>(&h1);
        out[i] = o;
    }
}

// Bc[o][n*16+r] = fp16(SCALE * lw[n] * lora_B[n][o][r])
__global__ void build_bc_kernel(const float* __restrict__ lora_B,
                                const float* __restrict__ lw) {
    int idx = blockIdx.x * blockDim.x + threadIdx.x;
    if (idx >= DOUT * NR) return;
    int o  = idx / NR;
    int nr = idx - o * NR;
    int n  = nr >> 4;
    int r  = nr & 15;
    g_Bch[idx] = __float2half_rn(
        (LORA_SCALE * lw[n]) * lora_B[((size_t)n * DOUT + o) * RANK + r]);
}

// ============================================================================
// GEMM1 (round-4 proven): fp16 mma, 64x128, BK=32, padded smem, 256 thr.
// ============================================================================
__global__ __launch_bounds__(256, 2)
void gemm1_f16(const __half* __restrict__ A1, int lda1,
               const __half* __restrict__ B1, int ldb1, int K1,
               __half* __restrict__ C, int ldc)
{
    constexpr int BM = 64, BN = 128;
    constexpr int S = 3;
    constexpr int MI = 2;
    constexpr int LDS_ = 40;
    constexpr int AST = BM * LDS_;
    constexpr int BST = BN * LDS_;
    constexpr int STG = AST + BST;

    extern __shared__ __half smem[];

    const int tid  = threadIdx.x;
    const int wid  = tid >> 5;
    const int lane = tid & 31;
    const int gid  = lane >> 2;
    const int tig  = lane & 3;
    const int warpRow = (wid >> 2) * 32;
    const int warpCol = (wid & 3) * 32;

    const size_t mBase = (size_t)blockIdx.y * BM;
    const int nIter = K1 / 32;
    const uint32_t smemB = s2u(smem);

    auto issue = [&](int k) {
        int slot = k % S;
        uint32_t aS = smemB + slot * STG * 2;
        uint32_t bS = aS + AST * 2;
        int kk = k * 32;
        {
            int idx = tid, row = idx >> 2, c8 = (idx & 3) << 3;
            cp16(aS + (row * LDS_ + c8) * 2,
                 A1 + (mBase + row) * (size_t)lda1 + kk + c8);
        }
        #pragma unroll
        for (int i = 0; i < 2; i++) {
            int idx = tid + i * 256, row = idx >> 2, c8 = (idx & 3) << 3;
            cp16(bS + (row * LDS_ + c8) * 2,
                 B1 + row * (size_t)ldb1 + kk + c8);
        }
    };

    float acc[MI][4][4];
    #pragma unroll
    for (int i = 0; i < MI; i++)
        #pragma unroll
        for (int j = 0; j < 4; j++)
            #pragma unroll
            for (int k = 0; k < 4; k++) acc[i][j][k] = 0.f;

    #pragma unroll
    for (int k = 0; k < S - 1; k++) { if (k < nIter) issue(k); cp_commit(); }

    for (int k = 0; k < nIter; k++) {
        cp_wait<S - 2>();
        __syncthreads();
        if (k + S - 1 < nIter) issue(k + S - 1);
        cp_commit();

        const __half* As = smem + (k % S) * STG;
        const __half* Bs = As + AST;

        #pragma unroll
        for (int ks = 0; ks < 2; ks++) {
            const int k0 = ks * 16;
            unsigned af[MI][4], bf[4][2];
            #pragma unroll
            for (int mi = 0; mi < MI; mi++) {
                const __half* a = As + (warpRow + mi * 16 + gid) * LDS_ + k0 + 2 * tig;
                af[mi][0] = *reinterpret_cast<const unsigned*>(a);
                af[mi][1] = *reinterpret_cast<const unsigned*>(a + 8 * LDS_);
                af[mi][2] = *reinterpret_cast<const unsigned*>(a + 8);
                af[mi][3] = *reinterpret_cast<const unsigned*>(a + 8 * LDS_ + 8);
            }
            #pragma unroll
            for (int ni = 0; ni < 4; ni++) {
                const __half* b = Bs + (warpCol + ni * 8 + gid) * LDS_ + k0 + 2 * tig;
                bf[ni][0] = *reinterpret_cast<const unsigned*>(b);
                bf[ni][1] = *reinterpret_cast<const unsigned*>(b + 8);
            }
            #pragma unroll
            for (int mi = 0; mi < MI; mi++)
                #pragma unroll
                for (int ni = 0; ni < 4; ni++) {
                    asm volatile(
                        "mma.sync.aligned.m16n8k16.row.col.f32.f16.f16.f32 "
                        "{%0,%1,%2,%3}, {%4,%5,%6,%7}, {%8,%9}, {%0,%1,%2,%3};"
                        : "+f"(acc[mi][ni][0]), "+f"(acc[mi][ni][1]),
                          "+f"(acc[mi][ni][2]), "+f"(acc[mi][ni][3])
                        : "r"(af[mi][0]), "r"(af[mi][1]),
                          "r"(af[mi][2]), "r"(af[mi][3]),
                          "r"(bf[ni][0]), "r"(bf[ni][1]));
                }
        }
    }

    #pragma unroll
    for (int mi = 0; mi < MI; mi++) {
        size_t row = mBase + warpRow + mi * 16 + gid;
        #pragma unroll
        for (int ni = 0; ni < 4; ni++) {
            size_t col = warpCol + ni * 8 + tig * 2;
            __half2 v0 = __floats2half2_rn(acc[mi][ni][0], acc[mi][ni][1]);
            __half2 v1 = __floats2half2_rn(acc[mi][ni][2], acc[mi][ni][3]);
            *reinterpret_cast<__half2*>(C + row * (size_t)ldc + col)       = v0;
            *reinterpret_cast<__half2*>(C + (row + 8) * (size_t)ldc + col) = v1;
        }
    }
}

// ============================================================================
// Main GEMM: 128x256 tile, BK=64, 256 threads (warps 2x4, warp tile 64x64),
// SW128 swizzle, ldmatrix, 3-stage cp.async pipeline, fragment pingpong.
// C = A1[M,K1]@B1[N,K1]^T + A2[M,K2]@B2[N,K2]^T (ld=NR) + bias
// ============================================================================
__global__ __launch_bounds__(256, 1)
void gemm_f16_big(const __half* __restrict__ A1, int lda1,
                  const __half* __restrict__ B1, int ldb1, int K1,
                  const __half* __restrict__ A2, const __half* __restrict__ B2,
                  int K2,
                  const float* __restrict__ bias,
                  float* __restrict__ C, int ldc)
{
    constexpr int BM = 128, BN = 256;
    constexpr int S  = 3;
    constexpr int AST = BM * 128;             // A stage bytes (128B rows)
    constexpr int STG = (BM + BN) * 128;      // 49152 B per stage
    constexpr int MI = 4, NI = 8;             // warp tile 64x64

    extern __shared__ __half smem[];

    const int tid  = threadIdx.x;
    const int wid  = tid >> 5;
    const int lane = tid & 31;
    const int gid  = lane >> 2;
    const int tig  = lane & 3;
    const int warpRow = (wid & 1) * 64;       // 2 warps in M
    const int warpCol = (wid >> 1) * 64;      // 4 warps in N

    const size_t mBase = (size_t)blockIdx.y * BM;
    const size_t nBase = (size_t)blockIdx.x * BN;

    const int n1    = K1 / 64;
    const int nIter = n1 + K2 / 64;
    const uint32_t tiles = s2u(smem);

    // ---- per-lane ldmatrix base offsets (SW128, pre-swizzled, ks=0) ----
    // swz128(row*128 + col) = row*128 + (col ^ ((row&7)<<4))
    const int quad = lane >> 3, l8 = lane & 7;
    const int arow = warpRow + ((quad & 1) << 3) + l8;
    const uint32_t aoff0 =
        (uint32_t)(arow * 128 + ((((quad >> 1) << 4)) ^ ((arow & 7) << 4)));
    const int brow = warpCol + ((quad >> 1) << 3) + l8;
    const uint32_t boff0 =
        (uint32_t)(AST + brow * 128 + ((((quad & 1) << 4)) ^ ((brow & 7) << 4)));

    auto issue = [&](int k) {
        int slot = k % S;
        uint32_t base = tiles + slot * STG;
        const __half *Ap, *Bp; int ldA, ldB, kk;
        if (k < n1) { Ap = A1; Bp = B1; ldA = lda1; ldB = ldb1; kk = k * 64; }
        else        { Ap = A2; Bp = B2; ldA = NR;   ldB = NR;   kk = (k - n1) * 64; }
        // A: 128 rows x 8 chunks = 1024 (4/thread)
        #pragma unroll
        for (int i = 0; i < 4; i++) {
            int idx = tid + i * 256, row = idx >> 3, c16 = idx & 7;
            cp16(base + row * 128 + ((c16 * 16) ^ ((row & 7) << 4)),
                 Ap + (mBase + row) * (size_t)ldA + kk + c16 * 8);
        }
        // B: 256 rows x 8 chunks = 2048 (8/thread)
        #pragma unroll
        for (int i = 0; i < 8; i++) {
            int idx = tid + i * 256, row = idx >> 3, c16 = idx & 7;
            cp16(base + AST + row * 128 + ((c16 * 16) ^ ((row & 7) << 4)),
                 Bp + (nBase + row) * (size_t)ldB + kk + c16 * 8);
        }
    };

    float acc[MI][NI][4];
    #pragma unroll
    for (int i = 0; i < MI; i++)
        #pragma unroll
        for (int j = 0; j < NI; j++)
            #pragma unroll
            for (int k = 0; k < 4; k++) acc[i][j][k] = 0.f;

    unsigned afX[MI][4], bgX[NI / 2][4];      // pingpong fragment buffers
    unsigned afY[MI][4], bgY[NI / 2][4];

    auto loadfrags = [&](uint32_t sbase, int ks,
                         unsigned af[MI][4], unsigned bg[NI / 2][4]) {
        const uint32_t kx = (uint32_t)(ks << 5);
        #pragma unroll
        for (int mi = 0; mi < MI; mi++)
            ldsm_x4(af[mi][0], af[mi][1], af[mi][2], af[mi][3],
                    (sbase + aoff0 + mi * 2048) ^ kx);
        #pragma unroll
        for (int g = 0; g < NI / 2; g++)
            ldsm_x4(bg[g][0], bg[g][1], bg[g][2], bg[g][3],
                    (sbase + boff0 + g * 2048) ^ kx);
    };

    auto domma = [&](unsigned af[MI][4], unsigned bg[NI / 2][4]) {
        #pragma unroll
        for (int mi = 0; mi < MI; mi++)
            #pragma unroll
            for (int ni = 0; ni < NI; ni++) {
                unsigned b0 = bg[ni >> 1][(ni & 1) * 2];
                unsigned b1 = bg[ni >> 1][(ni & 1) * 2 + 1];
                asm volatile(
                    "mma.sync.aligned.m16n8k16.row.col.f32.f16.f16.f32 "
                    "{%0,%1,%2,%3}, {%4,%5,%6,%7}, {%8,%9}, {%0,%1,%2,%3};"
                    : "+f"(acc[mi][ni][0]), "+f"(acc[mi][ni][1]),
                      "+f"(acc[mi][ni][2]), "+f"(acc[mi][ni][3])
                    : "r"(af[mi][0]), "r"(af[mi][1]),
                      "r"(af[mi][2]), "r"(af[mi][3]),
                      "r"(b0), "r"(b1));
            }
    };

    #pragma unroll
    for (int k = 0; k < S - 1; k++) { if (k < nIter) issue(k); cp_commit(); }

    for (int k = 0; k < nIter; k++) {
        cp_wait<S - 2>();
        __syncthreads();
        const uint32_t sbase = tiles + (k % S) * STG;

        loadfrags(sbase, 0, afX, bgX);
        if (k + S - 1 < nIter) issue(k + S - 1);
        cp_commit();
        loadfrags(sbase, 1, afY, bgY);
        domma(afX, bgX);
        loadfrags(sbase, 2, afX, bgX);
        domma(afY, bgY);
        loadfrags(sbase, 3, afY, bgY);
        domma(afX, bgX);
        domma(afY, bgY);
    }

    // ---- epilogue: +bias, float2 stores ----
    #pragma unroll
    for (int mi = 0; mi < MI; mi++) {
        size_t row = mBase + warpRow + mi * 16 + gid;
        #pragma unroll
        for (int ni = 0; ni < NI; ni++) {
            size_t col = nBase + warpCol + ni * 8 + tig * 2;
            float b0 = __ldg(bias + col);
            float b1 = __ldg(bias + col + 1);
            float2 v0, v1;
            v0.x = acc[mi][ni][0] + b0; v0.y = acc[mi][ni][1] + b1;
            v1.x = acc[mi][ni][2] + b0; v1.y = acc[mi][ni][3] + b1;
            *reinterpret_cast<float2*>(C + row * (size_t)ldc + col)       = v0;
            *reinterpret_cast<float2*>(C + (row + 8) * (size_t)ldc + col) = v1;
        }
    }
}

extern "C" void kernel_launch(void* const* d_in, const int* in_sizes, int n_in,
                              void* d_out, int out_size) {
    const float* x      = (const float*)d_in[0];
    const float* lora_A = (const float*)d_in[1];
    const float* lora_B = (const float*)d_in[2];
    const float* W      = (const float*)d_in[3];
    const float* bias   = (const float*)d_in[4];
    const float* lw     = (const float*)d_in[5];
    float* out = (float*)d_out;

    __half *xh, *Wh, *Ah, *hh, *bch;
    cudaGetSymbolAddress((void**)&xh,  g_xh);
    cudaGetSymbolAddress((void**)&Wh,  g_Wh);
    cudaGetSymbolAddress((void**)&Ah,  g_Ah);
    cudaGetSymbolAddress((void**)&hh,  g_hh);
    cudaGetSymbolAddress((void**)&bch, g_Bch);

    // 0) fp32 -> fp16 conversions
    f2h_kernel<<<4096, 256>>>((const float4*)x, (uint2*)xh, MTOT * DIN / 4);
    f2h_kernel<<<4096, 256>>>((const float4*)W, (uint2*)Wh, DOUT * DIN / 4);
    f2h_kernel<<<512,  256>>>((const float4*)lora_A, (uint2*)Ah, NR * DIN / 4);
    build_bc_kernel<<<(DOUT * NR + 255) / 256, 256>>>(lora_B, lw);

    constexpr int SMEM1   = 3 * (64 + 128) * 40 * 2;    // 46,080 B
    constexpr int SMEMBIG = 3 * (128 + 256) * 128;      // 147,456 B
    cudaFuncSetAttribute(gemm1_f16,
                         cudaFuncAttributeMaxDynamicSharedMemorySize, SMEM1);
    cudaFuncSetAttribute(gemm_f16_big,
                         cudaFuncAttributeMaxDynamicSharedMemorySize, SMEMBIG);

    // 1) h = x @ A_flat^T : [8192,128] fp16, K=4096
    gemm1_f16<<<dim3(1, MTOT / 64), 256, SMEM1>>>(
        xh, DIN, Ah, DIN, DIN, hh, NR);

    // 2) out = x @ W^T + h @ Bc^T + bias : [8192,4096] fp32
    gemm_f16_big<<<dim3(DOUT / 256, MTOT / 128), 256, SMEMBIG>>>(
        xh, DIN, Wh, DIN, DIN,
        hh, bch, NR,
        bias, out, DOUT);
}

// round 8
// speedup vs baseline: 3.2277x; 1.1424x over previous
#include <cuda_runtime.h>
#include <cuda_fp16.h>
#include <cstdint>

#define MTOT 8192      // B*S
#define DIN  4096
#define DOUT 4096
#define RANK 16
#define NR   128       // N_adapters * RANK
#define LORA_SCALE 2.0f

// ---- scratch (__device__ globals per allocation rules) ----
__device__ __half g_xh[MTOT * DIN];   // fp16 x
__device__ __half g_Wh[DOUT * DIN];   // fp16 W
__device__ __half g_Ah[NR * DIN];     // fp16 lora_A
__device__ __half g_hh[MTOT * NR];    // fp16 low-rank acts
__device__ __half g_Bch[DOUT * NR];   // fp16 coef-fused lora_B

__device__ __forceinline__ uint32_t s2u(const void* p) {
    return (uint32_t)__cvta_generic_to_shared(p);
}
__device__ __forceinline__ void cp16(uint32_t dst, const void* src) {
    asm volatile("cp.async.cg.shared.global [%0], [%1], 16;\n"
                 :: "r"(dst), "l"(src));
}
__device__ __forceinline__ void cp_commit() {
    asm volatile("cp.async.commit_group;" ::: "memory");
}
template<int N>
__device__ __forceinline__ void cp_wait() {
    asm volatile("cp.async.wait_group %0;" :: "n"(N) : "memory");
}
__device__ __forceinline__ void ldsm_x4(uint32_t& r0, uint32_t& r1,
                                        uint32_t& r2, uint32_t& r3, uint32_t a) {
    asm volatile("ldmatrix.sync.aligned.m8n8.x4.shared.b16 {%0,%1,%2,%3}, [%4];"
                 : "=r"(r0), "=r"(r1), "=r"(r2), "=r"(r3) : "r"(a));
}

// ---- fp32 -> fp16 conversion ----
__global__ void f2h_kernel(const float4* __restrict__ in,
                           uint2* __restrict__ out, int n4) {
    for (int i = blockIdx.x * blockDim.x + threadIdx.x; i < n4;
         i += gridDim.x * blockDim.x) {
        float4 v = in[i];
        __half2 h0 = __floats2half2_rn(v.x, v.y);
        __half2 h1 = __floats2half2_rn(v.z, v.w);
        uint2 o;
        o.x = *reinterpret_cast<unsigned*>(&h0);
        o.y = *reinterpret_cast<unsigned*>(&h1);
        out[i] = o;
    }
}

// Bc[o][n*16+r] = fp16(SCALE * lw[n] * lora_B[n][o][r])
__global__ void build_bc_kernel(const float* __restrict__ lora_B,
                                const float* __restrict__ lw) {
    int idx = blockIdx.x * blockDim.x + threadIdx.x;
    if (idx >= DOUT * NR) return;
    int o  = idx / NR;
    int nr = idx - o * NR;
    int n  = nr >> 4;
    int r  = nr & 15;
    g_Bch[idx] = __float2half_rn(
        (LORA_SCALE * lw[n]) * lora_B[((size_t)n * DOUT + o) * RANK + r]);
}

// ============================================================================
// GEMM1 (round-4 proven): fp16 mma, 64x128, BK=32, padded smem, 256 thr.
// ============================================================================
__global__ __launch_bounds__(256, 2)
void gemm1_f16(const __half* __restrict__ A1, int lda1,
               const __half* __restrict__ B1, int ldb1, int K1,
               __half* __restrict__ C, int ldc)
{
    constexpr int BM = 64, BN = 128;
    constexpr int S = 3;
    constexpr int MI = 2;
    constexpr int LDS_ = 40;
    constexpr int AST = BM * LDS_;
    constexpr int BST = BN * LDS_;
    constexpr int STG = AST + BST;

    extern __shared__ __half smem[];

    const int tid  = threadIdx.x;
    const int wid  = tid >> 5;
    const int lane = tid & 31;
    const int gid  = lane >> 2;
    const int tig  = lane & 3;
    const int warpRow = (wid >> 2) * 32;
    const int warpCol = (wid & 3) * 32;

    const size_t mBase = (size_t)blockIdx.y * BM;
    const int nIter = K1 / 32;
    const uint32_t smemB = s2u(smem);

    auto issue = [&](int k) {
        int slot = k % S;
        uint32_t aS = smemB + slot * STG * 2;
        uint32_t bS = aS + AST * 2;
        int kk = k * 32;
        {
            int idx = tid, row = idx >> 2, c8 = (idx & 3) << 3;
            cp16(aS + (row * LDS_ + c8) * 2,
                 A1 + (mBase + row) * (size_t)lda1 + kk + c8);
        }
        #pragma unroll
        for (int i = 0; i < 2; i++) {
            int idx = tid + i * 256, row = idx >> 2, c8 = (idx & 3) << 3;
            cp16(bS + (row * LDS_ + c8) * 2,
                 B1 + row * (size_t)ldb1 + kk + c8);
        }
    };

    float acc[MI][4][4];
    #pragma unroll
    for (int i = 0; i < MI; i++)
        #pragma unroll
        for (int j = 0; j < 4; j++)
            #pragma unroll
            for (int k = 0; k < 4; k++) acc[i][j][k] = 0.f;

    #pragma unroll
    for (int k = 0; k < S - 1; k++) { if (k < nIter) issue(k); cp_commit(); }

    for (int k = 0; k < nIter; k++) {
        cp_wait<S - 2>();
        __syncthreads();
        if (k + S - 1 < nIter) issue(k + S - 1);
        cp_commit();

        const __half* As = smem + (k % S) * STG;
        const __half* Bs = As + AST;

        #pragma unroll
        for (int ks = 0; ks < 2; ks++) {
            const int k0 = ks * 16;
            unsigned af[MI][4], bf[4][2];
            #pragma unroll
            for (int mi = 0; mi < MI; mi++) {
                const __half* a = As + (warpRow + mi * 16 + gid) * LDS_ + k0 + 2 * tig;
                af[mi][0] = *reinterpret_cast<const unsigned*>(a);
                af[mi][1] = *reinterpret_cast<const unsigned*>(a + 8 * LDS_);
                af[mi][2] = *reinterpret_cast<const unsigned*>(a + 8);
                af[mi][3] = *reinterpret_cast<const unsigned*>(a + 8 * LDS_ + 8);
            }
            #pragma unroll
            for (int ni = 0; ni < 4; ni++) {
                const __half* b = Bs + (warpCol + ni * 8 + gid) * LDS_ + k0 + 2 * tig;
                bf[ni][0] = *reinterpret_cast<const unsigned*>(b);
                bf[ni][1] = *reinterpret_cast<const unsigned*>(b + 8);
            }
            #pragma unroll
            for (int mi = 0; mi < MI; mi++)
                #pragma unroll
                for (int ni = 0; ni < 4; ni++) {
                    asm volatile(
                        "mma.sync.aligned.m16n8k16.row.col.f32.f16.f16.f32 "
                        "{%0,%1,%2,%3}, {%4,%5,%6,%7}, {%8,%9}, {%0,%1,%2,%3};"
                        : "+f"(acc[mi][ni][0]), "+f"(acc[mi][ni][1]),
                          "+f"(acc[mi][ni][2]), "+f"(acc[mi][ni][3])
                        : "r"(af[mi][0]), "r"(af[mi][1]),
                          "r"(af[mi][2]), "r"(af[mi][3]),
                          "r"(bf[ni][0]), "r"(bf[ni][1]));
                }
        }
    }

    #pragma unroll
    for (int mi = 0; mi < MI; mi++) {
        size_t row = mBase + warpRow + mi * 16 + gid;
        #pragma unroll
        for (int ni = 0; ni < 4; ni++) {
            size_t col = warpCol + ni * 8 + tig * 2;
            __half2 v0 = __floats2half2_rn(acc[mi][ni][0], acc[mi][ni][1]);
            __half2 v1 = __floats2half2_rn(acc[mi][ni][2], acc[mi][ni][3]);
            *reinterpret_cast<__half2*>(C + row * (size_t)ldc + col)       = v0;
            *reinterpret_cast<__half2*>(C + (row + 8) * (size_t)ldc + col) = v1;
        }
    }
}

// ============================================================================
// Main GEMM: 128x256 tile, BK=64, 256 threads (warps 2x4, warp tile 64x64),
// SW128 swizzle, ldmatrix, 4-stage cp.async pipeline with cross-iteration
// fragment prefetch and spread cp.async issue.
// C = A1[M,K1]@B1[N,K1]^T + A2[M,K2]@B2[N,K2]^T (ld=NR) + bias
// ============================================================================
__global__ __launch_bounds__(256, 1)
void gemm_f16_big(const __half* __restrict__ A1, int lda1,
                  const __half* __restrict__ B1, int ldb1, int K1,
                  const __half* __restrict__ A2, const __half* __restrict__ B2,
                  int K2,
                  const float* __restrict__ bias,
                  float* __restrict__ C, int ldc)
{
    constexpr int BM = 128, BN = 256;
    constexpr int S  = 4;
    constexpr int AST = BM * 128;             // A stage bytes (128B rows)
    constexpr int STG = (BM + BN) * 128;      // 49152 B per stage
    constexpr int MI = 4, NI = 8;             // warp tile 64x64

    extern __shared__ __half smem[];

    const int tid  = threadIdx.x;
    const int wid  = tid >> 5;
    const int lane = tid & 31;
    const int gid  = lane >> 2;
    const int tig  = lane & 3;
    const int warpRow = (wid & 1) * 64;       // 2 warps in M
    const int warpCol = (wid >> 1) * 64;      // 4 warps in N

    const size_t mBase = (size_t)blockIdx.y * BM;
    const size_t nBase = (size_t)blockIdx.x * BN;

    const int n1    = K1 / 64;
    const int nIter = n1 + K2 / 64;
    const uint32_t tiles = s2u(smem);

    // ---- per-lane ldmatrix base offsets (SW128, pre-swizzled, ks=0) ----
    const int quad = lane >> 3, l8 = lane & 7;
    const int arow = warpRow + ((quad & 1) << 3) + l8;
    const uint32_t aoff0 =
        (uint32_t)(arow * 128 + ((((quad >> 1) << 4)) ^ ((arow & 7) << 4)));
    const int brow = warpCol + ((quad >> 1) << 3) + l8;
    const uint32_t boff0 =
        (uint32_t)(AST + brow * 128 + ((((quad & 1) << 4)) ^ ((brow & 7) << 4)));

    // part 0: A tile (4 cp16/thread); part 1: B rows 0-127; part 2: B rows 128-255
    auto issue = [&](int k, int part) {
        int slot = k % S;
        uint32_t base = tiles + slot * STG;
        const __half *Ap, *Bp; int ldA, ldB, kk;
        if (k < n1) { Ap = A1; Bp = B1; ldA = lda1; ldB = ldb1; kk = k * 64; }
        else        { Ap = A2; Bp = B2; ldA = NR;   ldB = NR;   kk = (k - n1) * 64; }
        if (part == 0) {
            #pragma unroll
            for (int i = 0; i < 4; i++) {
                int idx = tid + i * 256, row = idx >> 3, c16 = idx & 7;
                cp16(base + row * 128 + ((c16 * 16) ^ ((row & 7) << 4)),
                     Ap + (mBase + row) * (size_t)ldA + kk + c16 * 8);
            }
        } else {
            #pragma unroll
            for (int i = 0; i < 4; i++) {
                int idx = tid + (part - 1) * 1024 + i * 256;
                int row = idx >> 3, c16 = idx & 7;
                cp16(base + AST + row * 128 + ((c16 * 16) ^ ((row & 7) << 4)),
                     Bp + (nBase + row) * (size_t)ldB + kk + c16 * 8);
            }
        }
    };

    float acc[MI][NI][4];
    #pragma unroll
    for (int i = 0; i < MI; i++)
        #pragma unroll
        for (int j = 0; j < NI; j++)
            #pragma unroll
            for (int k = 0; k < 4; k++) acc[i][j][k] = 0.f;

    unsigned afX[MI][4], bgX[NI / 2][4];      // pingpong fragment buffers
    unsigned afY[MI][4], bgY[NI / 2][4];

    auto loadfrags = [&](uint32_t sbase, int ks,
                         unsigned af[MI][4], unsigned bg[NI / 2][4]) {
        const uint32_t kx = (uint32_t)(ks << 5);
        #pragma unroll
        for (int mi = 0; mi < MI; mi++)
            ldsm_x4(af[mi][0], af[mi][1], af[mi][2], af[mi][3],
                    (sbase + aoff0 + mi * 2048) ^ kx);
        #pragma unroll
        for (int g = 0; g < NI / 2; g++)
            ldsm_x4(bg[g][0], bg[g][1], bg[g][2], bg[g][3],
                    (sbase + boff0 + g * 2048) ^ kx);
    };

    auto domma = [&](unsigned af[MI][4], unsigned bg[NI / 2][4]) {
        #pragma unroll
        for (int mi = 0; mi < MI; mi++)
            #pragma unroll
            for (int ni = 0; ni < NI; ni++) {
                unsigned b0 = bg[ni >> 1][(ni & 1) * 2];
                unsigned b1 = bg[ni >> 1][(ni & 1) * 2 + 1];
                asm volatile(
                    "mma.sync.aligned.m16n8k16.row.col.f32.f16.f16.f32 "
                    "{%0,%1,%2,%3}, {%4,%5,%6,%7}, {%8,%9}, {%0,%1,%2,%3};"
                    : "+f"(acc[mi][ni][0]), "+f"(acc[mi][ni][1]),
                      "+f"(acc[mi][ni][2]), "+f"(acc[mi][ni][3])
                    : "r"(af[mi][0]), "r"(af[mi][1]),
                      "r"(af[mi][2]), "r"(af[mi][3]),
                      "r"(b0), "r"(b1));
            }
    };

    // prologue: stages 0..S-2 (3 groups in flight)
    #pragma unroll
    for (int k = 0; k < S - 1; k++) {
        if (k < nIter) { issue(k, 0); issue(k, 1); issue(k, 2); }
        cp_commit();
    }
    cp_wait<S - 2>();          // stage 0 resident
    __syncthreads();
    loadfrags(tiles, 0, afX, bgX);

    for (int k = 0; k < nIter; k++) {
        const uint32_t sbase = tiles + (k % S) * STG;
        const uint32_t snext = tiles + ((k + 1) % S) * STG;
        const bool more = (k + S - 1 < nIter);

        loadfrags(sbase, 1, afY, bgY);
        if (more) issue(k + S - 1, 0);
        domma(afX, bgX);                     // ks0

        loadfrags(sbase, 2, afX, bgX);
        if (more) issue(k + S - 1, 1);
        domma(afY, bgY);                     // ks1

        loadfrags(sbase, 3, afY, bgY);
        if (more) issue(k + S - 1, 2);
        domma(afX, bgX);                     // ks2

        cp_commit();
        cp_wait<S - 2>();                    // stage k+1 resident
        __syncthreads();                     // all stage-k reads complete
        loadfrags(snext, 0, afX, bgX);       // prefetch next ks0 (junk on last iter: unused)
        domma(afY, bgY);                     // ks3
    }

    // ---- epilogue: +bias, float2 stores ----
    #pragma unroll
    for (int mi = 0; mi < MI; mi++) {
        size_t row = mBase + warpRow + mi * 16 + gid;
        #pragma unroll
        for (int ni = 0; ni < NI; ni++) {
            size_t col = nBase + warpCol + ni * 8 + tig * 2;
            float b0 = __ldg(bias + col);
            float b1 = __ldg(bias + col + 1);
            float2 v0, v1;
            v0.x = acc[mi][ni][0] + b0; v0.y = acc[mi][ni][1] + b1;
            v1.x = acc[mi][ni][2] + b0; v1.y = acc[mi][ni][3] + b1;
            *reinterpret_cast<float2*>(C + row * (size_t)ldc + col)       = v0;
            *reinterpret_cast<float2*>(C + (row + 8) * (size_t)ldc + col) = v1;
        }
    }
}

extern "C" void kernel_launch(void* const* d_in, const int* in_sizes, int n_in,
                              void* d_out, int out_size) {
    const float* x      = (const float*)d_in[0];
    const float* lora_A = (const float*)d_in[1];
    const float* lora_B = (const float*)d_in[2];
    const float* W      = (const float*)d_in[3];
    const float* bias   = (const float*)d_in[4];
    const float* lw     = (const float*)d_in[5];
    float* out = (float*)d_out;

    __half *xh, *Wh, *Ah, *hh, *bch;
    cudaGetSymbolAddress((void**)&xh,  g_xh);
    cudaGetSymbolAddress((void**)&Wh,  g_Wh);
    cudaGetSymbolAddress((void**)&Ah,  g_Ah);
    cudaGetSymbolAddress((void**)&hh,  g_hh);
    cudaGetSymbolAddress((void**)&bch, g_Bch);

    // 0) fp32 -> fp16 conversions
    f2h_kernel<<<4096, 256>>>((const float4*)x, (uint2*)xh, MTOT * DIN / 4);
    f2h_kernel<<<4096, 256>>>((const float4*)W, (uint2*)Wh, DOUT * DIN / 4);
    f2h_kernel<<<512,  256>>>((const float4*)lora_A, (uint2*)Ah, NR * DIN / 4);
    build_bc_kernel<<<(DOUT * NR + 255) / 256, 256>>>(lora_B, lw);

    constexpr int SMEM1   = 3 * (64 + 128) * 40 * 2;    // 46,080 B
    constexpr int SMEMBIG = 4 * (128 + 256) * 128;      // 196,608 B
    cudaFuncSetAttribute(gemm1_f16,
                         cudaFuncAttributeMaxDynamicSharedMemorySize, SMEM1);
    cudaFuncSetAttribute(gemm_f16_big,
                         cudaFuncAttributeMaxDynamicSharedMemorySize, SMEMBIG);

    // 1) h = x @ A_flat^T : [8192,128] fp16, K=4096
    gemm1_f16<<<dim3(1, MTOT / 64), 256, SMEM1>>>(
        xh, DIN, Ah, DIN, DIN, hh, NR);

    // 2) out = x @ W^T + h @ Bc^T + bias : [8192,4096] fp32
    gemm_f16_big<<<dim3(DOUT / 256, MTOT / 128), 256, SMEMBIG>>>(
        xh, DIN, Wh, DIN, DIN,
        hh, bch, NR,
        bias, out, DOUT);
}

// round 11
// speedup vs baseline: 3.2469x; 1.0060x over previous
#include <cuda_runtime.h>
#include <cuda_fp16.h>
#include <cstdint>

#define MTOT 8192      // B*S
#define DIN  4096
#define DOUT 4096
#define RANK 16
#define NR   128       // N_adapters * RANK
#define LORA_SCALE 2.0f

// ---- scratch (__device__ globals per allocation rules) ----
__device__ __half g_xh[MTOT * DIN];   // fp16 x (written by gemm1 fused convert)
__device__ __half g_Wh[DOUT * DIN];   // fp16 W
__device__ __half g_Ah[NR * DIN];     // fp16 lora_A
__device__ __half g_hh[MTOT * NR];    // fp16 low-rank acts
__device__ __half g_Bch[DOUT * NR];   // fp16 coef-fused lora_B

__device__ __forceinline__ uint32_t s2u(const void* p) {
    return (uint32_t)__cvta_generic_to_shared(p);
}
__device__ __forceinline__ void cp16(uint32_t dst, const void* src) {
    asm volatile("cp.async.cg.shared.global [%0], [%1], 16;\n"
                 :: "r"(dst), "l"(src));
}
__device__ __forceinline__ void cp_commit() {
    asm volatile("cp.async.commit_group;" ::: "memory");
}
template<int N>
__device__ __forceinline__ void cp_wait() {
    asm volatile("cp.async.wait_group %0;" :: "n"(N) : "memory");
}
__device__ __forceinline__ void ldsm_x4(uint32_t& r0, uint32_t& r1,
                                        uint32_t& r2, uint32_t& r3, uint32_t a) {
    asm volatile("ldmatrix.sync.aligned.m8n8.x4.shared.b16 {%0,%1,%2,%3}, [%4];"
                 : "=r"(r0), "=r"(r1), "=r"(r2), "=r"(r3) : "r"(a));
}
__device__ __forceinline__ uint4 cvt8(float4 v0, float4 v1) {
    __half2 h0 = __floats2half2_rn(v0.x, v0.y);
    __half2 h1 = __floats2half2_rn(v0.z, v0.w);
    __half2 h2 = __floats2half2_rn(v1.x, v1.y);
    __half2 h3 = __floats2half2_rn(v1.z, v1.w);
    uint4 u;
    u.x = *reinterpret_cast<unsigned*>(&h0);
    u.y = *reinterpret_cast<unsigned*>(&h1);
    u.z = *reinterpret_cast<unsigned*>(&h2);
    u.w = *reinterpret_cast<unsigned*>(&h3);
    return u;
}

// ---- fp32 -> fp16 conversion (still used for lora_A) ----
__global__ void f2h_kernel(const float4* __restrict__ in,
                           uint2* __restrict__ out, int n4) {
    for (int i = blockIdx.x * blockDim.x + threadIdx.x; i < n4;
         i += gridDim.x * blockDim.x) {
        float4 v = in[i];
        __half2 h0 = __floats2half2_rn(v.x, v.y);
        __half2 h1 = __floats2half2_rn(v.z, v.w);
        uint2 o;
        o.x = *reinterpret_cast<unsigned*>(&h0);
        o.y = *reinterpret_cast<unsigned*>(&h1);
        out[i] = o;
    }
}

// Bc[o][n*16+r] = fp16(SCALE * lw[n] * lora_B[n][o][r])
__global__ void build_bc_kernel(const float* __restrict__ lora_B,
                                const float* __restrict__ lw) {
    int idx = blockIdx.x * blockDim.x + threadIdx.x;
    if (idx >= DOUT * NR) return;
    int o  = idx / NR;
    int nr = idx - o * NR;
    int n  = nr >> 4;
    int r  = nr & 15;
    g_Bch[idx] = __float2half_rn(
        (LORA_SCALE * lw[n]) * lora_B[((size_t)n * DOUT + o) * RANK + r]);
}

// ============================================================================
// GEMM1 + fused conversions. blockIdx.y < MBLK: compute h = x@A^T while
// converting x fp32->fp16 (A-path: LDG+cvt+STS, and STG to g_xh).
// blockIdx.y >= MBLK: convert W fp32->fp16 (grid-stride), co-scheduled.
// ============================================================================
#define G1_MBLK 128
#define G1_WBLK 64

__global__ __launch_bounds__(256, 2)
void gemm1_fused(const float* __restrict__ x,
                 const __half* __restrict__ Ah,
                 __half* __restrict__ hh,
                 __half* __restrict__ xh,
                 const float* __restrict__ W,
                 __half* __restrict__ Wh)
{
    constexpr int BM = 64, BN = 128;
    constexpr int S = 3;
    constexpr int MI = 2;
    constexpr int LDS_ = 40;
    constexpr int AST = BM * LDS_;
    constexpr int STG_ = AST + BN * LDS_;

    const int tid = threadIdx.x;

    // ---- co-scheduled W conversion blocks ----
    if (blockIdx.y >= G1_MBLK) {
        int base = (blockIdx.y - G1_MBLK) * 256 + tid;
        const float4* in = (const float4*)W;
        uint2* out = (uint2*)Wh;
        constexpr int n4 = DOUT * DIN / 4;
        for (int i = base; i < n4; i += G1_WBLK * 256) {
            float4 v = in[i];
            __half2 h0 = __floats2half2_rn(v.x, v.y);
            __half2 h1 = __floats2half2_rn(v.z, v.w);
            uint2 o;
            o.x = *reinterpret_cast<unsigned*>(&h0);
            o.y = *reinterpret_cast<unsigned*>(&h1);
            out[i] = o;
        }
        return;
    }

    extern __shared__ __half smem[];

    const int wid  = tid >> 5;
    const int lane = tid & 31;
    const int gid  = lane >> 2;
    const int tig  = lane & 3;
    const int warpRow = (wid >> 2) * 32;
    const int warpCol = (wid & 3) * 32;

    const size_t mBase = (size_t)blockIdx.y * BM;
    const int nIter = DIN / 32;                 // 128
    const uint32_t smemB = s2u(smem);

    // per-thread A coords: row 0..63, 8-half chunk
    const int arow = tid >> 2;
    const int ac8  = (tid & 3) << 3;
    const float* xsrc = x + (mBase + arow) * (size_t)DIN + ac8;
    __half*      xdst = xh + (mBase + arow) * (size_t)DIN + ac8;

    auto issueB = [&](int k) {
        int slot = k % S;
        uint32_t bS = smemB + (slot * STG_ + AST) * 2;
        int kk = k * 32;
        #pragma unroll
        for (int i = 0; i < 2; i++) {
            int idx = tid + i * 256, row = idx >> 2, c8 = (idx & 3) << 3;
            cp16(bS + (row * LDS_ + c8) * 2,
                 Ah + row * (size_t)DIN + kk + c8);
        }
    };
    auto ldgA = [&](int k, float4& v0, float4& v1) {
        const float* p = xsrc + k * 32;
        v0 = __ldg((const float4*)p);
        v1 = __ldg((const float4*)(p + 4));
    };
    auto stsA = [&](int k, float4 v0, float4 v1) {
        uint4 u = cvt8(v0, v1);
        *reinterpret_cast<uint4*>(smem + (k % S) * STG_ + arow * LDS_ + ac8) = u;
        *reinterpret_cast<uint4*>(xdst + (size_t)k * 32) = u;
    };

    float acc[MI][4][4];
    #pragma unroll
    for (int i = 0; i < MI; i++)
        #pragma unroll
        for (int j = 0; j < 4; j++)
            #pragma unroll
            for (int k = 0; k < 4; k++) acc[i][j][k] = 0.f;

    // prologue
    issueB(0); cp_commit();
    issueB(1); cp_commit();
    float4 a0, a1;
    ldgA(0, a0, a1); stsA(0, a0, a1);
    ldgA(1, a0, a1);                            // held for slot 1

    for (int k = 0; k < nIter; k++) {
        cp_wait<1>();
        __syncthreads();
        if (k + 1 < nIter) stsA(k + 1, a0, a1);
        if (k + 2 < nIter) { issueB(k + 2); ldgA(k + 2, a0, a1); }
        cp_commit();

        const __half* As = smem + (k % S) * STG_;
        const __half* Bs = As + AST;

        #pragma unroll
        for (int ks = 0; ks < 2; ks++) {
            const int k0 = ks * 16;
            unsigned af[MI][4], bf[4][2];
            #pragma unroll
            for (int mi = 0; mi < MI; mi++) {
                const __half* a = As + (warpRow + mi * 16 + gid) * LDS_ + k0 + 2 * tig;
                af[mi][0] = *reinterpret_cast<const unsigned*>(a);
                af[mi][1] = *reinterpret_cast<const unsigned*>(a + 8 * LDS_);
                af[mi][2] = *reinterpret_cast<const unsigned*>(a + 8);
                af[mi][3] = *reinterpret_cast<const unsigned*>(a + 8 * LDS_ + 8);
            }
            #pragma unroll
            for (int ni = 0; ni < 4; ni++) {
                const __half* b = Bs + (warpCol + ni * 8 + gid) * LDS_ + k0 + 2 * tig;
                bf[ni][0] = *reinterpret_cast<const unsigned*>(b);
                bf[ni][1] = *reinterpret_cast<const unsigned*>(b + 8);
            }
            #pragma unroll
            for (int mi = 0; mi < MI; mi++)
                #pragma unroll
                for (int ni = 0; ni < 4; ni++) {
                    asm volatile(
                        "mma.sync.aligned.m16n8k16.row.col.f32.f16.f16.f32 "
                        "{%0,%1,%2,%3}, {%4,%5,%6,%7}, {%8,%9}, {%0,%1,%2,%3};"
                        : "+f"(acc[mi][ni][0]), "+f"(acc[mi][ni][1]),
                          "+f"(acc[mi][ni][2]), "+f"(acc[mi][ni][3])
                        : "r"(af[mi][0]), "r"(af[mi][1]),
                          "r"(af[mi][2]), "r"(af[mi][3]),
                          "r"(bf[ni][0]), "r"(bf[ni][1]));
                }
        }
    }

    #pragma unroll
    for (int mi = 0; mi < MI; mi++) {
        size_t row = mBase + warpRow + mi * 16 + gid;
        #pragma unroll
        for (int ni = 0; ni < 4; ni++) {
            size_t col = warpCol + ni * 8 + tig * 2;
            __half2 v0 = __floats2half2_rn(acc[mi][ni][0], acc[mi][ni][1]);
            __half2 v1 = __floats2half2_rn(acc[mi][ni][2], acc[mi][ni][3]);
            *reinterpret_cast<__half2*>(hh + row * NR + col)       = v0;
            *reinterpret_cast<__half2*>(hh + (row + 8) * NR + col) = v1;
        }
    }
}

// ============================================================================
// Main GEMM (round-8 proven): 128x256 tile, BK=64, 256 threads, warp 64x64,
// SW128, ldmatrix, 4-stage cp.async pipeline + cross-iteration prefetch.
// ============================================================================
__global__ __launch_bounds__(256, 1)
void gemm_f16_big(const __half* __restrict__ A1, int lda1,
                  const __half* __restrict__ B1, int ldb1, int K1,
                  const __half* __restrict__ A2, const __half* __restrict__ B2,
                  int K2,
                  const float* __restrict__ bias,
                  float* __restrict__ C, int ldc)
{
    constexpr int BM = 128, BN = 256;
    constexpr int S  = 4;
    constexpr int AST = BM * 128;
    constexpr int STG = (BM + BN) * 128;
    constexpr int MI = 4, NI = 8;

    extern __shared__ __half smem[];

    const int tid  = threadIdx.x;
    const int wid  = tid >> 5;
    const int lane = tid & 31;
    const int gid  = lane >> 2;
    const int tig  = lane & 3;
    const int warpRow = (wid & 1) * 64;
    const int warpCol = (wid >> 1) * 64;

    const size_t mBase = (size_t)blockIdx.y * BM;
    const size_t nBase = (size_t)blockIdx.x * BN;

    const int n1    = K1 / 64;
    const int nIter = n1 + K2 / 64;
    const uint32_t tiles = s2u(smem);

    const int quad = lane >> 3, l8 = lane & 7;
    const int arow = warpRow + ((quad & 1) << 3) + l8;
    const uint32_t aoff0 =
        (uint32_t)(arow * 128 + ((((quad >> 1) << 4)) ^ ((arow & 7) << 4)));
    const int brow = warpCol + ((quad >> 1) << 3) + l8;
    const uint32_t boff0 =
        (uint32_t)(AST + brow * 128 + ((((quad & 1) << 4)) ^ ((brow & 7) << 4)));

    auto issue = [&](int k, int part) {
        int slot = k % S;
        uint32_t base = tiles + slot * STG;
        const __half *Ap, *Bp; int ldA, ldB, kk;
        if (k < n1) { Ap = A1; Bp = B1; ldA = lda1; ldB = ldb1; kk = k * 64; }
        else        { Ap = A2; Bp = B2; ldA = NR;   ldB = NR;   kk = (k - n1) * 64; }
        if (part == 0) {
            #pragma unroll
            for (int i = 0; i < 4; i++) {
                int idx = tid + i * 256, row = idx >> 3, c16 = idx & 7;
                cp16(base + row * 128 + ((c16 * 16) ^ ((row & 7) << 4)),
                     Ap + (mBase + row) * (size_t)ldA + kk + c16 * 8);
            }
        } else {
            #pragma unroll
            for (int i = 0; i < 4; i++) {
                int idx = tid + (part - 1) * 1024 + i * 256;
                int row = idx >> 3, c16 = idx & 7;
                cp16(base + AST + row * 128 + ((c16 * 16) ^ ((row & 7) << 4)),
                     Bp + (nBase + row) * (size_t)ldB + kk + c16 * 8);
            }
        }
    };

    float acc[MI][NI][4];
    #pragma unroll
    for (int i = 0; i < MI; i++)
        #pragma unroll
        for (int j = 0; j < NI; j++)
            #pragma unroll
            for (int k = 0; k < 4; k++) acc[i][j][k] = 0.f;

    unsigned afX[MI][4], bgX[NI / 2][4];
    unsigned afY[MI][4], bgY[NI / 2][4];

    auto loadfrags = [&](uint32_t sbase, int ks,
                         unsigned af[MI][4], unsigned bg[NI / 2][4]) {
        const uint32_t kx = (uint32_t)(ks << 5);
        #pragma unroll
        for (int mi = 0; mi < MI; mi++)
            ldsm_x4(af[mi][0], af[mi][1], af[mi][2], af[mi][3],
                    (sbase + aoff0 + mi * 2048) ^ kx);
        #pragma unroll
        for (int g = 0; g < NI / 2; g++)
            ldsm_x4(bg[g][0], bg[g][1], bg[g][2], bg[g][3],
                    (sbase + boff0 + g * 2048) ^ kx);
    };

    auto domma = [&](unsigned af[MI][4], unsigned bg[NI / 2][4]) {
        #pragma unroll
        for (int mi = 0; mi < MI; mi++)
            #pragma unroll
            for (int ni = 0; ni < NI; ni++) {
                unsigned b0 = bg[ni >> 1][(ni & 1) * 2];
                unsigned b1 = bg[ni >> 1][(ni & 1) * 2 + 1];
                asm volatile(
                    "mma.sync.aligned.m16n8k16.row.col.f32.f16.f16.f32 "
                    "{%0,%1,%2,%3}, {%4,%5,%6,%7}, {%8,%9}, {%0,%1,%2,%3};"
                    : "+f"(acc[mi][ni][0]), "+f"(acc[mi][ni][1]),
                      "+f"(acc[mi][ni][2]), "+f"(acc[mi][ni][3])
                    : "r"(af[mi][0]), "r"(af[mi][1]),
                      "r"(af[mi][2]), "r"(af[mi][3]),
                      "r"(b0), "r"(b1));
            }
    };

    #pragma unroll
    for (int k = 0; k < S - 1; k++) {
        if (k < nIter) { issue(k, 0); issue(k, 1); issue(k, 2); }
        cp_commit();
    }
    cp_wait<S - 2>();
    __syncthreads();
    loadfrags(tiles, 0, afX, bgX);

    for (int k = 0; k < nIter; k++) {
        const uint32_t sbase = tiles + (k % S) * STG;
        const uint32_t snext = tiles + ((k + 1) % S) * STG;
        const bool more = (k + S - 1 < nIter);

        loadfrags(sbase, 1, afY, bgY);
        if (more) issue(k + S - 1, 0);
        domma(afX, bgX);

        loadfrags(sbase, 2, afX, bgX);
        if (more) issue(k + S - 1, 1);
        domma(afY, bgY);

        loadfrags(sbase, 3, afY, bgY);
        if (more) issue(k + S - 1, 2);
        domma(afX, bgX);

        cp_commit();
        cp_wait<S - 2>();
        __syncthreads();
        loadfrags(snext, 0, afX, bgX);
        domma(afY, bgY);
    }

    #pragma unroll
    for (int mi = 0; mi < MI; mi++) {
        size_t row = mBase + warpRow + mi * 16 + gid;
        #pragma unroll
        for (int ni = 0; ni < NI; ni++) {
            size_t col = nBase + warpCol + ni * 8 + tig * 2;
            float b0 = __ldg(bias + col);
            float b1 = __ldg(bias + col + 1);
            float2 v0, v1;
            v0.x = acc[mi][ni][0] + b0; v0.y = acc[mi][ni][1] + b1;
            v1.x = acc[mi][ni][2] + b0; v1.y = acc[mi][ni][3] + b1;
            *reinterpret_cast<float2*>(C + row * (size_t)ldc + col)       = v0;
            *reinterpret_cast<float2*>(C + (row + 8) * (size_t)ldc + col) = v1;
        }
    }
}

extern "C" void kernel_launch(void* const* d_in, const int* in_sizes, int n_in,
                              void* d_out, int out_size) {
    const float* x      = (const float*)d_in[0];
    const float* lora_A = (const float*)d_in[1];
    const float* lora_B = (const float*)d_in[2];
    const float* W      = (const float*)d_in[3];
    const float* bias   = (const float*)d_in[4];
    const float* lw     = (const float*)d_in[5];
    float* out = (float*)d_out;

    __half *xh, *Wh, *Ah, *hh, *bch;
    cudaGetSymbolAddress((void**)&xh,  g_xh);
    cudaGetSymbolAddress((void**)&Wh,  g_Wh);
    cudaGetSymbolAddress((void**)&Ah,  g_Ah);
    cudaGetSymbolAddress((void**)&hh,  g_hh);
    cudaGetSymbolAddress((void**)&bch, g_Bch);

    // 0) small preps (must precede gemm1: it reads Ah)
    build_bc_kernel<<<(DOUT * NR + 255) / 256, 256>>>(lora_B, lw);
    f2h_kernel<<<512, 256>>>((const float4*)lora_A, (uint2*)Ah, NR * DIN / 4);

    constexpr int SMEM1   = 3 * (64 + 128) * 40 * 2;    // 46,080 B
    constexpr int SMEMBIG = 4 * (128 + 256) * 128;      // 196,608 B
    cudaFuncSetAttribute(gemm1_fused,
                         cudaFuncAttributeMaxDynamicSharedMemorySize, SMEM1);
    cudaFuncSetAttribute(gemm_f16_big,
                         cudaFuncAttributeMaxDynamicSharedMemorySize, SMEMBIG);

    // 1) h = x @ A^T (+ x fp32->fp16 into xh) ∥ W fp32->fp16 into Wh
    gemm1_fused<<<dim3(1, G1_MBLK + G1_WBLK), 256, SMEM1>>>(
        x, Ah, hh, xh, W, Wh);

    // 2) out = x @ W^T + h @ Bc^T + bias
    gemm_f16_big<<<dim3(DOUT / 256, MTOT / 128), 256, SMEMBIG>>>(
        xh, DIN, Wh, DIN, DIN,
        hh, bch, NR,
        bias, out, DOUT);
}